// round 1
// baseline (speedup 1.0000x reference)
#include <cuda_runtime.h>

#define D_MODEL   1024
#define N_HEADS   16
#define HEAD_DIM  64
#define SEQ_L     2048          // NT*LD = 16*128
#define BATCH     2
#define BL        (BATCH*SEQ_L) // 4096 rows for the big GEMMs
#define KV_STRIDE (SEQ_L*HEAD_DIM)

// scratch (static device arrays: allocation-free per harness rules)
__device__ float g_q[BATCH*N_HEADS*SEQ_L*HEAD_DIM];   // 16 MB
__device__ float g_attn[(size_t)BL*D_MODEL];          // 16 MB

// ---------------------------------------------------------------------------
// C = A(4096,1024) @ W(1024,1024)^T + bias
// mode 0: C[row*1024+col] (flat)       mode 1: head-major (B,H,L,hd)
// 128x128x16 tiles, 256 threads, 8x8 micro-tile, transposed smem + float4
// ---------------------------------------------------------------------------
__global__ __launch_bounds__(256) void gemm_bias_kernel(
    const float* __restrict__ A, const float* __restrict__ W,
    const float* __restrict__ bias, float* __restrict__ C, int mode)
{
    __shared__ float As[16*132];
    __shared__ float Bs[16*132];
    const int tid = threadIdx.x;
    const int tx = tid & 15, ty = tid >> 4;
    const int m0 = blockIdx.y * 128;
    const int n0 = blockIdx.x * 128;

    float acc[8][8];
#pragma unroll
    for (int i = 0; i < 8; i++)
#pragma unroll
        for (int j = 0; j < 8; j++) acc[i][j] = 0.f;

    const int lr = tid >> 2;   // 0..63
    const int c4 = tid & 3;    // 0..3

    for (int kt = 0; kt < 1024; kt += 16) {
#pragma unroll
        for (int e = 0; e < 2; e++) {
            int rr = lr + e*64;
            float4 av = *(const float4*)&A[(size_t)(m0+rr)*1024 + kt + c4*4];
            As[(c4*4+0)*132 + rr] = av.x;
            As[(c4*4+1)*132 + rr] = av.y;
            As[(c4*4+2)*132 + rr] = av.z;
            As[(c4*4+3)*132 + rr] = av.w;
            float4 wv = *(const float4*)&W[(size_t)(n0+rr)*1024 + kt + c4*4];
            Bs[(c4*4+0)*132 + rr] = wv.x;
            Bs[(c4*4+1)*132 + rr] = wv.y;
            Bs[(c4*4+2)*132 + rr] = wv.z;
            Bs[(c4*4+3)*132 + rr] = wv.w;
        }
        __syncthreads();
#pragma unroll
        for (int kk = 0; kk < 16; kk++) {
            float4 a0 = *(float4*)&As[kk*132 + ty*8];
            float4 a1 = *(float4*)&As[kk*132 + ty*8 + 4];
            float4 b0 = *(float4*)&Bs[kk*132 + tx*8];
            float4 b1 = *(float4*)&Bs[kk*132 + tx*8 + 4];
            float a[8] = {a0.x,a0.y,a0.z,a0.w,a1.x,a1.y,a1.z,a1.w};
            float b[8] = {b0.x,b0.y,b0.z,b0.w,b1.x,b1.y,b1.z,b1.w};
#pragma unroll
            for (int i = 0; i < 8; i++)
#pragma unroll
                for (int j = 0; j < 8; j++)
                    acc[i][j] += a[i]*b[j];
        }
        __syncthreads();
    }

#pragma unroll
    for (int i = 0; i < 8; i++) {
        int row = m0 + ty*8 + i;
#pragma unroll
        for (int j4 = 0; j4 < 2; j4++) {
            int col = n0 + tx*8 + j4*4;
            float4 o;
            o.x = acc[i][j4*4+0] + bias[col+0];
            o.y = acc[i][j4*4+1] + bias[col+1];
            o.z = acc[i][j4*4+2] + bias[col+2];
            o.w = acc[i][j4*4+3] + bias[col+3];
            if (mode == 0) {
                *(float4*)&C[(size_t)row*1024 + col] = o;
            } else {
                int b = row >> 11;       // /SEQ_L
                int l = row & 2047;
                int h = col >> 6;        // /HEAD_DIM
                int d = col & 63;
                *(float4*)&C[(size_t)((b*N_HEADS + h)*SEQ_L + l)*HEAD_DIM + d] = o;
            }
        }
    }
}

// ---------------------------------------------------------------------------
// RoPE in-place on q and k, (B,H,L,hd) layout. One thread per rotation pair.
// total pairs = B*H*L*32 = 2,097,152
// ---------------------------------------------------------------------------
__global__ __launch_bounds__(256) void rope_kernel(
    float* __restrict__ q, float* __restrict__ k, const int* __restrict__ dt)
{
    int idx = blockIdx.x * blockDim.x + threadIdx.x;
    int i  = idx & 31;               // pair index within head dim
    int l  = (idx >> 5) & (SEQ_L-1); // position
    int bh = idx >> 16;              // b*H+h
    float t = (float)dt[l >> 7];     // LD = 128 spatial tokens per timestep
    // inv_freq = ROPE_BASE^(-i/32), ln(100000) = 11.512925464970229
    float ang = t * __expf(-(float)i * (11.512925464970229f / 32.0f));
    float s, c;
    __sincosf(ang, &s, &c);
    size_t base = (size_t)(bh*SEQ_L + l)*HEAD_DIM + i;
    float q0 = q[base], q1 = q[base+32];
    q[base]    = q0*c - q1*s;
    q[base+32] = q1*c + q0*s;
    float k0 = k[base], k1 = k[base+32];
    k[base]    = k0*c - k1*s;
    k[base+32] = k1*c + k0*s;
}

// ---------------------------------------------------------------------------
// Flash attention fp32: block = 64 q-rows of one (b,h); Tk = 32 keys/tile.
// 256 threads. S phase: 4x2 micro; PV phase: 4x4 micro. Online softmax with
// 16-lane shfl reductions. All smem accesses vectorized. 44 KB static smem.
// Output written to g_attn in (b, l, h*64+d) flat layout for the final GEMM.
// ---------------------------------------------------------------------------
__global__ __launch_bounds__(256) void flash_kernel(
    const float* __restrict__ q, const float* __restrict__ k,
    const float* __restrict__ v, float* __restrict__ o)
{
    __shared__ float qs[64*68];   // q transposed: [d][r]
    __shared__ float ks[64*36];   // k transposed: [d][kc]
    __shared__ float vs[32*68];   // v: [kc][d]
    __shared__ float ps[32*68];   // P transposed: [kc][r]

    const int tid = threadIdx.x;
    const int tx = tid & 15, ty = tid >> 4;
    const int b = blockIdx.z, h = blockIdx.y;
    const int qbase = blockIdx.x * 64;
    const float* qh = q + (size_t)(b*N_HEADS + h)*KV_STRIDE;
    const float* kh = k + (size_t)(b*N_HEADS + h)*KV_STRIDE;
    const float* vh = v + (size_t)(b*N_HEADS + h)*KV_STRIDE;

    // load q tile transposed
#pragma unroll
    for (int e = 0; e < 4; e++) {
        int flat4 = tid + e*256;
        int r  = flat4 >> 4;
        int d4 = flat4 & 15;
        float4 qv = *(const float4*)&qh[(size_t)(qbase+r)*HEAD_DIM + d4*4];
        qs[(d4*4+0)*68 + r] = qv.x;
        qs[(d4*4+1)*68 + r] = qv.y;
        qs[(d4*4+2)*68 + r] = qv.z;
        qs[(d4*4+3)*68 + r] = qv.w;
    }

    float acc[4][4];
#pragma unroll
    for (int i = 0; i < 4; i++)
#pragma unroll
        for (int j = 0; j < 4; j++) acc[i][j] = 0.f;
    float m[4]    = {-1e30f, -1e30f, -1e30f, -1e30f};
    float lsum[4] = {0.f, 0.f, 0.f, 0.f};
    const float scale = 0.125f;   // 1/sqrt(64)

    for (int kt = 0; kt < SEQ_L; kt += 32) {
        __syncthreads();  // protect ps/vs reads of previous iter
#pragma unroll
        for (int e = 0; e < 2; e++) {
            int flat4 = tid + e*256;
            int kr = flat4 >> 4;   // 0..31
            int d4 = flat4 & 15;
            float4 kv = *(const float4*)&kh[(size_t)(kt+kr)*HEAD_DIM + d4*4];
            ks[(d4*4+0)*36 + kr] = kv.x;
            ks[(d4*4+1)*36 + kr] = kv.y;
            ks[(d4*4+2)*36 + kr] = kv.z;
            ks[(d4*4+3)*36 + kr] = kv.w;
            float4 vv = *(const float4*)&vh[(size_t)(kt+kr)*HEAD_DIM + d4*4];
            *(float4*)&vs[kr*68 + d4*4] = vv;
        }
        __syncthreads();

        // S = q @ k^T  (rows ty*4..+3, cols tx*2..+1)
        float s0[4] = {0.f,0.f,0.f,0.f};
        float s1[4] = {0.f,0.f,0.f,0.f};
#pragma unroll
        for (int d = 0; d < 64; d++) {
            float4 a  = *(float4*)&qs[d*68 + ty*4];
            float2 bb = *(float2*)&ks[d*36 + tx*2];
            s0[0] += a.x*bb.x; s1[0] += a.x*bb.y;
            s0[1] += a.y*bb.x; s1[1] += a.y*bb.y;
            s0[2] += a.z*bb.x; s1[2] += a.z*bb.y;
            s0[3] += a.w*bb.x; s1[3] += a.w*bb.y;
        }

        // online softmax per row (replicated across the 16 tx lanes)
#pragma unroll
        for (int i = 0; i < 4; i++) {
            float v0 = s0[i]*scale, v1 = s1[i]*scale;
            float mt = fmaxf(v0, v1);
#pragma unroll
            for (int off = 1; off < 16; off <<= 1)
                mt = fmaxf(mt, __shfl_xor_sync(0xffffffffu, mt, off));
            float mn = fmaxf(m[i], mt);
            float alpha = __expf(m[i] - mn);
            float p0 = __expf(v0 - mn);
            float p1 = __expf(v1 - mn);
            float rs = p0 + p1;
#pragma unroll
            for (int off = 1; off < 16; off <<= 1)
                rs += __shfl_xor_sync(0xffffffffu, rs, off);
            lsum[i] = lsum[i]*alpha + rs;
            m[i] = mn;
            acc[i][0] *= alpha; acc[i][1] *= alpha;
            acc[i][2] *= alpha; acc[i][3] *= alpha;
            ps[(tx*2+0)*68 + ty*4 + i] = p0;
            ps[(tx*2+1)*68 + ty*4 + i] = p1;
        }
        __syncthreads();

        // O += P @ V  (rows ty*4..+3, dims tx*4..+3)
#pragma unroll
        for (int kr = 0; kr < 32; kr++) {
            float4 p4 = *(float4*)&ps[kr*68 + ty*4];
            float4 v4 = *(float4*)&vs[kr*68 + tx*4];
            acc[0][0]+=p4.x*v4.x; acc[0][1]+=p4.x*v4.y; acc[0][2]+=p4.x*v4.z; acc[0][3]+=p4.x*v4.w;
            acc[1][0]+=p4.y*v4.x; acc[1][1]+=p4.y*v4.y; acc[1][2]+=p4.y*v4.z; acc[1][3]+=p4.y*v4.w;
            acc[2][0]+=p4.z*v4.x; acc[2][1]+=p4.z*v4.y; acc[2][2]+=p4.z*v4.z; acc[2][3]+=p4.z*v4.w;
            acc[3][0]+=p4.w*v4.x; acc[3][1]+=p4.w*v4.y; acc[3][2]+=p4.w*v4.z; acc[3][3]+=p4.w*v4.w;
        }
    }

#pragma unroll
    for (int i = 0; i < 4; i++) {
        int row = qbase + ty*4 + i;
        float inv = 1.0f / lsum[i];
        float4 ov;
        ov.x = acc[i][0]*inv; ov.y = acc[i][1]*inv;
        ov.z = acc[i][2]*inv; ov.w = acc[i][3]*inv;
        *(float4*)&o[(size_t)(b*SEQ_L + row)*D_MODEL + h*HEAD_DIM + tx*4] = ov;
    }
}

// ---------------------------------------------------------------------------
extern "C" void kernel_launch(void* const* d_in, const int* in_sizes, int n_in,
                              void* d_out, int out_size)
{
    const float* x  = (const float*)d_in[0];
    const int*   dt = (const int*)  d_in[1];
    const float* Wq = (const float*)d_in[2];
    const float* bq = (const float*)d_in[3];
    const float* Wk = (const float*)d_in[4];
    const float* bk = (const float*)d_in[5];
    const float* Wv = (const float*)d_in[6];
    const float* bv = (const float*)d_in[7];
    const float* Wo = (const float*)d_in[8];
    const float* bo = (const float*)d_in[9];

    float* outp  = (float*)d_out;
    float* k_out = outp  + (size_t)BL * D_MODEL;   // k slice (B,H,L,hd), post-RoPE
    float* v_out = k_out + (size_t)BL * D_MODEL;   // v slice (B,H,L,hd)

    float *qbuf = nullptr, *abuf = nullptr;
    cudaGetSymbolAddress((void**)&qbuf, g_q);
    cudaGetSymbolAddress((void**)&abuf, g_attn);

    dim3 gemm_grid(8, 32);   // N/128 x M/128

    // projections (head-major epilogue)
    gemm_bias_kernel<<<gemm_grid, 256>>>(x, Wq, bq, qbuf,  1);
    gemm_bias_kernel<<<gemm_grid, 256>>>(x, Wk, bk, k_out, 1);
    gemm_bias_kernel<<<gemm_grid, 256>>>(x, Wv, bv, v_out, 1);

    // RoPE on q and k (k in-place inside d_out — reference returns roped k)
    rope_kernel<<<8192, 256>>>(qbuf, k_out, dt);

    // attention -> g_attn in (b, l, h*hd+d) layout
    flash_kernel<<<dim3(SEQ_L/64, N_HEADS, BATCH), 256>>>(qbuf, k_out, v_out, abuf);

    // output projection (flat epilogue)
    gemm_bias_kernel<<<gemm_grid, 256>>>(abuf, Wo, bo, outp, 0);
}

// round 3
// speedup vs baseline: 2.5930x; 2.5930x over previous
#include <cuda_runtime.h>
#include <cuda_fp16.h>
#include <cstdint>

#define D_MODEL   1024
#define N_HEADS   16
#define HEAD_DIM  64
#define SEQ_L     2048          // NT*LD = 16*128
#define BATCH     2
#define BL        (BATCH*SEQ_L)
#define KV_STRIDE (SEQ_L*HEAD_DIM)

// scratch (static device arrays: allocation-free per harness rules)
__device__ float g_q[BATCH*N_HEADS*SEQ_L*HEAD_DIM];   // 16 MB
__device__ float g_attn[(size_t)BL*D_MODEL];          // 16 MB

// ===========================================================================
// helpers
// ===========================================================================
__device__ __forceinline__ uint32_t smem_u32(const void* p) {
    uint32_t a;
    asm("{ .reg .u64 t; cvta.to.shared.u64 t, %1; cvt.u32.u64 %0, t; }"
        : "=r"(a) : "l"(p));
    return a;
}
__device__ __forceinline__ void ldsm_x4(uint32_t* r, uint32_t addr) {
    asm volatile("ldmatrix.sync.aligned.m8n8.x4.shared.b16 {%0,%1,%2,%3}, [%4];"
                 : "=r"(r[0]), "=r"(r[1]), "=r"(r[2]), "=r"(r[3]) : "r"(addr));
}
__device__ __forceinline__ void ldsm_x2(uint32_t& r0, uint32_t& r1, uint32_t addr) {
    asm volatile("ldmatrix.sync.aligned.m8n8.x2.shared.b16 {%0,%1}, [%2];"
                 : "=r"(r0), "=r"(r1) : "r"(addr));
}
__device__ __forceinline__ void ldsm_x2t(uint32_t& r0, uint32_t& r1, uint32_t addr) {
    asm volatile("ldmatrix.sync.aligned.m8n8.x2.trans.shared.b16 {%0,%1}, [%2];"
                 : "=r"(r0), "=r"(r1) : "r"(addr));
}
__device__ __forceinline__ void mma16816(float* c,
    uint32_t a0, uint32_t a1, uint32_t a2, uint32_t a3, uint32_t b0, uint32_t b1) {
    asm volatile(
        "mma.sync.aligned.m16n8k16.row.col.f32.f16.f16.f32 "
        "{%0,%1,%2,%3}, {%4,%5,%6,%7}, {%8,%9}, {%0,%1,%2,%3};"
        : "+f"(c[0]), "+f"(c[1]), "+f"(c[2]), "+f"(c[3])
        : "r"(a0), "r"(a1), "r"(a2), "r"(a3), "r"(b0), "r"(b1));
}
__device__ __forceinline__ uint32_t pack_h2(float a, float b) {
    __half2 h = __floats2half2_rn(a, b);
    return *(uint32_t*)&h;
}
__device__ __forceinline__ void hsplit(float x, __half& h, __half& l) {
    h = __float2half_rn(x);
    l = __float2half_rn(x - __half2float(h));
}

// ===========================================================================
// GEMM via mma.sync fp16x3:  C[4096,1024] = A[4096,1024] @ W[1024,1024]^T + b
// CTA 128x128, 8 warps (4Mx2N), warp tile 32x64, k-chunk 32.
// mode 0: flat    mode 1: head-major (B,H,L,hd)
// ===========================================================================
#define TSTR 40   // smem row stride in halves (conflict-free for ldmatrix)

__global__ __launch_bounds__(256, 1) void gemm_mma(
    const float* __restrict__ A, const float* __restrict__ W,
    const float* __restrict__ bias, float* __restrict__ C, int mode)
{
    __shared__ __half Ah[128*TSTR], Al[128*TSTR];
    __shared__ __half Bh[128*TSTR], Bl[128*TSTR];

    const int tid  = threadIdx.x;
    const int lane = tid & 31;
    const int warp = tid >> 5;
    const int wm = warp >> 1;   // 0..3
    const int wn = warp & 1;    // 0..1
    const int m0 = blockIdx.y * 128;
    const int n0 = blockIdx.x * 128;

    const uint32_t ah_b = smem_u32(Ah), al_b = smem_u32(Al);
    const uint32_t bh_b = smem_u32(Bh), bl_b = smem_u32(Bl);
    const int l4 = lane & 15;

    float acc[2][8][4];
#pragma unroll
    for (int i = 0; i < 2; i++)
#pragma unroll
        for (int j = 0; j < 8; j++)
#pragma unroll
            for (int c = 0; c < 4; c++) acc[i][j][c] = 0.f;

    for (int kt = 0; kt < 1024; kt += 32) {
        __syncthreads();
#pragma unroll
        for (int e = 0; e < 4; e++) {
            int f4 = tid + e * 256;           // 0..1023
            int row = f4 >> 3, c4 = (f4 & 7) * 4;
            float4 av = *(const float4*)&A[(size_t)(m0 + row) * 1024 + kt + c4];
            __half h0, h1, h2, h3, q0, q1, q2, q3;
            hsplit(av.x, h0, q0); hsplit(av.y, h1, q1);
            hsplit(av.z, h2, q2); hsplit(av.w, h3, q3);
            *(__half2*)&Ah[row*TSTR + c4]     = __halves2half2(h0, h1);
            *(__half2*)&Ah[row*TSTR + c4 + 2] = __halves2half2(h2, h3);
            *(__half2*)&Al[row*TSTR + c4]     = __halves2half2(q0, q1);
            *(__half2*)&Al[row*TSTR + c4 + 2] = __halves2half2(q2, q3);
            float4 wv = *(const float4*)&W[(size_t)(n0 + row) * 1024 + kt + c4];
            hsplit(wv.x, h0, q0); hsplit(wv.y, h1, q1);
            hsplit(wv.z, h2, q2); hsplit(wv.w, h3, q3);
            *(__half2*)&Bh[row*TSTR + c4]     = __halves2half2(h0, h1);
            *(__half2*)&Bh[row*TSTR + c4 + 2] = __halves2half2(h2, h3);
            *(__half2*)&Bl[row*TSTR + c4]     = __halves2half2(q0, q1);
            *(__half2*)&Bl[row*TSTR + c4 + 2] = __halves2half2(q2, q3);
        }
        __syncthreads();

#pragma unroll
        for (int s = 0; s < 2; s++) {
            uint32_t afh[2][4], afl[2][4];
#pragma unroll
            for (int mt = 0; mt < 2; mt++) {
                uint32_t off = (uint32_t)((wm*32 + mt*16 + (lane & 15)) * TSTR
                                          + s*16 + (lane >> 4) * 8) * 2;
                ldsm_x4(afh[mt], ah_b + off);
                ldsm_x4(afl[mt], al_b + off);
            }
#pragma unroll
            for (int nt = 0; nt < 8; nt++) {
                uint32_t off = (uint32_t)((wn*64 + nt*8 + (l4 & 7)) * TSTR
                                          + s*16 + (l4 >> 3) * 8) * 2;
                uint32_t b0h, b1h, b0l, b1l;
                ldsm_x2(b0h, b1h, bh_b + off);
                ldsm_x2(b0l, b1l, bl_b + off);
#pragma unroll
                for (int mt = 0; mt < 2; mt++) {
                    mma16816(acc[mt][nt], afh[mt][0], afh[mt][1], afh[mt][2], afh[mt][3], b0h, b1h);
                    mma16816(acc[mt][nt], afh[mt][0], afh[mt][1], afh[mt][2], afh[mt][3], b0l, b1l);
                    mma16816(acc[mt][nt], afl[mt][0], afl[mt][1], afl[mt][2], afl[mt][3], b0h, b1h);
                }
            }
        }
    }

    // epilogue
#pragma unroll
    for (int mt = 0; mt < 2; mt++) {
        int r_lo = m0 + wm*32 + mt*16 + (lane >> 2);
        int r_hi = r_lo + 8;
#pragma unroll
        for (int nt = 0; nt < 8; nt++) {
            int col = n0 + wn*64 + nt*8 + (lane & 3) * 2;
            float bx = bias[col], by = bias[col + 1];
            float2 lo = make_float2(acc[mt][nt][0] + bx, acc[mt][nt][1] + by);
            float2 hi = make_float2(acc[mt][nt][2] + bx, acc[mt][nt][3] + by);
            if (mode == 0) {
                *(float2*)&C[(size_t)r_lo * 1024 + col] = lo;
                *(float2*)&C[(size_t)r_hi * 1024 + col] = hi;
            } else {
                int h = col >> 6, d = col & 63;
                int b_lo = r_lo >> 11, l_lo = r_lo & 2047;
                int b_hi = r_hi >> 11, l_hi = r_hi & 2047;
                *(float2*)&C[(size_t)((b_lo*N_HEADS + h)*SEQ_L + l_lo)*HEAD_DIM + d] = lo;
                *(float2*)&C[(size_t)((b_hi*N_HEADS + h)*SEQ_L + l_hi)*HEAD_DIM + d] = hi;
            }
        }
    }
}

// ===========================================================================
// RoPE in-place on q and k, (B,H,L,hd) layout.
// ===========================================================================
__global__ __launch_bounds__(256) void rope_kernel(
    float* __restrict__ q, float* __restrict__ k, const int* __restrict__ dt)
{
    int idx = blockIdx.x * blockDim.x + threadIdx.x;
    int i  = idx & 31;
    int l  = (idx >> 5) & (SEQ_L-1);
    int bh = idx >> 16;
    float t = (float)dt[l >> 7];
    float ang = t * __expf(-(float)i * (11.512925464970229f / 32.0f));
    float s, c;
    __sincosf(ang, &s, &c);
    size_t base = (size_t)(bh*SEQ_L + l)*HEAD_DIM + i;
    float q0 = q[base], q1 = q[base+32];
    q[base]    = q0*c - q1*s;
    q[base+32] = q1*c + q0*s;
    float k0 = k[base], k1 = k[base+32];
    k[base]    = k0*c - k1*s;
    k[base+32] = k1*c + k0*s;
}

// ===========================================================================
// Flash attention via mma.sync (FA2-style).
// 128 threads (4 warps); block = 64 q-rows of one (b,h); Tk = 64.
// S = QK^T fp16x3; softmax on fragments; PV = P(fp16) x (Vh+Vl).
// Warp w owns q-rows [16w,16w+16).
// smem halves, row stride 72 (conflict-free ldmatrix).
// ===========================================================================
#define FSTR 72
#define FTILE (64*FSTR)        // 4608 halves
#define FLASH_SMEM (6*FTILE*2) // 55296 bytes

__global__ __launch_bounds__(128) void flash_mma(
    const float* __restrict__ q, const float* __restrict__ k,
    const float* __restrict__ v, float* __restrict__ o)
{
    extern __shared__ __half fsm[];
    __half* Qh = fsm;
    __half* Ql = fsm + FTILE;
    __half* Kh = fsm + 2*FTILE;
    __half* Kl = fsm + 3*FTILE;
    __half* Vh = fsm + 4*FTILE;
    __half* Vl = fsm + 5*FTILE;

    const int tid  = threadIdx.x;
    const int lane = tid & 31;
    const int warp = tid >> 5;
    const int l4   = lane & 15;
    const int b = blockIdx.z, h = blockIdx.y;
    const int qbase = blockIdx.x * 64;

    const float* qp = q + (size_t)(b*N_HEADS + h)*KV_STRIDE;
    const float* kp = k + (size_t)(b*N_HEADS + h)*KV_STRIDE;
    const float* vp = v + (size_t)(b*N_HEADS + h)*KV_STRIDE;

    // ---- load Q tile (64x64) once, split into hi/lo halves ----
#pragma unroll
    for (int e = 0; e < 8; e++) {
        int f4 = tid + e * 128;          // 0..1023
        int row = f4 >> 4, c4 = (f4 & 15) * 4;
        float4 qv = *(const float4*)&qp[(size_t)(qbase + row) * HEAD_DIM + c4];
        __half h0, h1, h2, h3, q0, q1, q2, q3;
        hsplit(qv.x, h0, q0); hsplit(qv.y, h1, q1);
        hsplit(qv.z, h2, q2); hsplit(qv.w, h3, q3);
        *(__half2*)&Qh[row*FSTR + c4]     = __halves2half2(h0, h1);
        *(__half2*)&Qh[row*FSTR + c4 + 2] = __halves2half2(h2, h3);
        *(__half2*)&Ql[row*FSTR + c4]     = __halves2half2(q0, q1);
        *(__half2*)&Ql[row*FSTR + c4 + 2] = __halves2half2(q2, q3);
    }
    __syncthreads();

    const uint32_t qh_b = smem_u32(Qh), ql_b = smem_u32(Ql);
    const uint32_t kh_b = smem_u32(Kh), kl_b = smem_u32(Kl);
    const uint32_t vh_b = smem_u32(Vh), vl_b = smem_u32(Vl);

    // hoist Q fragments: 4 k-steps x 4 regs, hi and lo
    uint32_t qfh[4][4], qfl[4][4];
#pragma unroll
    for (int s = 0; s < 4; s++) {
        uint32_t off = (uint32_t)((warp*16 + (lane & 15)) * FSTR
                                  + s*16 + (lane >> 4) * 8) * 2;
        ldsm_x4(qfh[s], qh_b + off);
        ldsm_x4(qfl[s], ql_b + off);
    }

    float oacc[8][4];
#pragma unroll
    for (int n = 0; n < 8; n++)
#pragma unroll
        for (int c = 0; c < 4; c++) oacc[n][c] = 0.f;
    float m_lo = -1e30f, m_hi = -1e30f;
    float l_lo = 0.f, l_hi = 0.f;
    const float scale = 0.125f;   // 1/sqrt(64)

    for (int kt = 0; kt < SEQ_L; kt += 64) {
        __syncthreads();   // previous iteration's reads of Kh..Vl done
#pragma unroll
        for (int e = 0; e < 8; e++) {
            int f4 = tid + e * 128;
            int row = f4 >> 4, c4 = (f4 & 15) * 4;
            float4 kv = *(const float4*)&kp[(size_t)(kt + row) * HEAD_DIM + c4];
            __half h0, h1, h2, h3, q0, q1, q2, q3;
            hsplit(kv.x, h0, q0); hsplit(kv.y, h1, q1);
            hsplit(kv.z, h2, q2); hsplit(kv.w, h3, q3);
            *(__half2*)&Kh[row*FSTR + c4]     = __halves2half2(h0, h1);
            *(__half2*)&Kh[row*FSTR + c4 + 2] = __halves2half2(h2, h3);
            *(__half2*)&Kl[row*FSTR + c4]     = __halves2half2(q0, q1);
            *(__half2*)&Kl[row*FSTR + c4 + 2] = __halves2half2(q2, q3);
            float4 vv = *(const float4*)&vp[(size_t)(kt + row) * HEAD_DIM + c4];
            hsplit(vv.x, h0, q0); hsplit(vv.y, h1, q1);
            hsplit(vv.z, h2, q2); hsplit(vv.w, h3, q3);
            *(__half2*)&Vh[row*FSTR + c4]     = __halves2half2(h0, h1);
            *(__half2*)&Vh[row*FSTR + c4 + 2] = __halves2half2(h2, h3);
            *(__half2*)&Vl[row*FSTR + c4]     = __halves2half2(q0, q1);
            *(__half2*)&Vl[row*FSTR + c4 + 2] = __halves2half2(q2, q3);
        }
        __syncthreads();

        // ---- S = Q K^T (64 keys): 8 n-tiles x 4 k-steps x 3 terms ----
        float sacc[8][4];
#pragma unroll
        for (int j = 0; j < 8; j++)
#pragma unroll
            for (int c = 0; c < 4; c++) sacc[j][c] = 0.f;
#pragma unroll
        for (int j = 0; j < 8; j++) {
#pragma unroll
            for (int s = 0; s < 4; s++) {
                uint32_t off = (uint32_t)((j*8 + (l4 & 7)) * FSTR
                                          + s*16 + (l4 >> 3) * 8) * 2;
                uint32_t b0h, b1h, b0l, b1l;
                ldsm_x2(b0h, b1h, kh_b + off);
                ldsm_x2(b0l, b1l, kl_b + off);
                mma16816(sacc[j], qfh[s][0], qfh[s][1], qfh[s][2], qfh[s][3], b0h, b1h);
                mma16816(sacc[j], qfh[s][0], qfh[s][1], qfh[s][2], qfh[s][3], b0l, b1l);
                mma16816(sacc[j], qfl[s][0], qfl[s][1], qfl[s][2], qfl[s][3], b0h, b1h);
            }
        }

        // ---- online softmax on fragments ----
        float mx0 = -1e30f, mx1 = -1e30f;
#pragma unroll
        for (int j = 0; j < 8; j++) {
            mx0 = fmaxf(mx0, fmaxf(sacc[j][0], sacc[j][1]));
            mx1 = fmaxf(mx1, fmaxf(sacc[j][2], sacc[j][3]));
        }
        mx0 = fmaxf(mx0, __shfl_xor_sync(0xffffffffu, mx0, 1));
        mx0 = fmaxf(mx0, __shfl_xor_sync(0xffffffffu, mx0, 2));
        mx1 = fmaxf(mx1, __shfl_xor_sync(0xffffffffu, mx1, 1));
        mx1 = fmaxf(mx1, __shfl_xor_sync(0xffffffffu, mx1, 2));
        float mn0 = fmaxf(m_lo, mx0 * scale);
        float mn1 = fmaxf(m_hi, mx1 * scale);
        float al0 = __expf(m_lo - mn0);
        float al1 = __expf(m_hi - mn1);
        m_lo = mn0; m_hi = mn1;
        float sum0 = 0.f, sum1 = 0.f;
#pragma unroll
        for (int j = 0; j < 8; j++) {
            sacc[j][0] = __expf(sacc[j][0] * scale - mn0);
            sacc[j][1] = __expf(sacc[j][1] * scale - mn0);
            sacc[j][2] = __expf(sacc[j][2] * scale - mn1);
            sacc[j][3] = __expf(sacc[j][3] * scale - mn1);
            sum0 += sacc[j][0] + sacc[j][1];
            sum1 += sacc[j][2] + sacc[j][3];
        }
        sum0 += __shfl_xor_sync(0xffffffffu, sum0, 1);
        sum0 += __shfl_xor_sync(0xffffffffu, sum0, 2);
        sum1 += __shfl_xor_sync(0xffffffffu, sum1, 1);
        sum1 += __shfl_xor_sync(0xffffffffu, sum1, 2);
        l_lo = l_lo * al0 + sum0;
        l_hi = l_hi * al1 + sum1;
#pragma unroll
        for (int n = 0; n < 8; n++) {
            oacc[n][0] *= al0; oacc[n][1] *= al0;
            oacc[n][2] *= al1; oacc[n][3] *= al1;
        }

        // ---- PV: P (fp16, from fragments) x (Vh + Vl) ----
#pragma unroll
        for (int t = 0; t < 4; t++) {
            uint32_t a0 = pack_h2(sacc[2*t][0],   sacc[2*t][1]);
            uint32_t a1 = pack_h2(sacc[2*t][2],   sacc[2*t][3]);
            uint32_t a2 = pack_h2(sacc[2*t+1][0], sacc[2*t+1][1]);
            uint32_t a3 = pack_h2(sacc[2*t+1][2], sacc[2*t+1][3]);
#pragma unroll
            for (int n = 0; n < 8; n++) {
                uint32_t off = (uint32_t)((t*16 + (l4 & 7) + (l4 >> 3) * 8) * FSTR
                                          + n*8) * 2;
                uint32_t b0, b1;
                ldsm_x2t(b0, b1, vh_b + off);
                mma16816(oacc[n], a0, a1, a2, a3, b0, b1);
                ldsm_x2t(b0, b1, vl_b + off);
                mma16816(oacc[n], a0, a1, a2, a3, b0, b1);
            }
        }
    }

    // ---- normalize + write out (flat (b, l, h*64+d) for final GEMM) ----
    float inv0 = 1.0f / l_lo;
    float inv1 = 1.0f / l_hi;
    int r_lo = qbase + warp*16 + (lane >> 2);
    int r_hi = r_lo + 8;
#pragma unroll
    for (int n = 0; n < 8; n++) {
        int col = h*HEAD_DIM + n*8 + (lane & 3)*2;
        *(float2*)&o[(size_t)(b*SEQ_L + r_lo)*D_MODEL + col] =
            make_float2(oacc[n][0]*inv0, oacc[n][1]*inv0);
        *(float2*)&o[(size_t)(b*SEQ_L + r_hi)*D_MODEL + col] =
            make_float2(oacc[n][2]*inv1, oacc[n][3]*inv1);
    }
}

// ---------------------------------------------------------------------------
extern "C" void kernel_launch(void* const* d_in, const int* in_sizes, int n_in,
                              void* d_out, int out_size)
{
    const float* x  = (const float*)d_in[0];
    const int*   dt = (const int*)  d_in[1];
    const float* Wq = (const float*)d_in[2];
    const float* bq = (const float*)d_in[3];
    const float* Wk = (const float*)d_in[4];
    const float* bk = (const float*)d_in[5];
    const float* Wv = (const float*)d_in[6];
    const float* bv = (const float*)d_in[7];
    const float* Wo = (const float*)d_in[8];
    const float* bo = (const float*)d_in[9];

    float* outp  = (float*)d_out;
    float* k_out = outp  + (size_t)BL * D_MODEL;   // k slice (B,H,L,hd), post-RoPE
    float* v_out = k_out + (size_t)BL * D_MODEL;   // v slice (B,H,L,hd)

    float *qbuf = nullptr, *abuf = nullptr;
    cudaGetSymbolAddress((void**)&qbuf, g_q);
    cudaGetSymbolAddress((void**)&abuf, g_attn);

    cudaFuncSetAttribute(flash_mma, cudaFuncAttributeMaxDynamicSharedMemorySize,
                         FLASH_SMEM);

    dim3 ggrid(8, 32);   // N/128 x M/128

    gemm_mma<<<ggrid, 256>>>(x, Wq, bq, qbuf,  1);
    gemm_mma<<<ggrid, 256>>>(x, Wk, bk, k_out, 1);
    gemm_mma<<<ggrid, 256>>>(x, Wv, bv, v_out, 1);

    rope_kernel<<<8192, 256>>>(qbuf, k_out, dt);

    flash_mma<<<dim3(SEQ_L/64, N_HEADS, BATCH), 128, FLASH_SMEM>>>(
        qbuf, k_out, v_out, abuf);

    gemm_mma<<<ggrid, 256>>>(abuf, Wo, bo, outp, 0);
}

// round 4
// speedup vs baseline: 3.0451x; 1.1743x over previous
#include <cuda_runtime.h>
#include <cuda_fp16.h>
#include <cstdint>

#define D_MODEL   1024
#define N_HEADS   16
#define HEAD_DIM  64
#define SEQ_L     2048
#define BATCH     2
#define BL        (BATCH*SEQ_L)
#define KV_STRIDE (SEQ_L*HEAD_DIM)
#define NELEM     ((size_t)BL*D_MODEL)   // 4M

// static scratch (allocation-free)
__device__ float  g_q [BATCH*N_HEADS*SEQ_L*HEAD_DIM];        // q fp32 (pre-rope)
__device__ __half g_xh[NELEM], g_xl[NELEM];                  // x split
__device__ __half g_wh[4][1024*1024], g_wl[4][1024*1024];    // Wq,Wk,Wv,Wo split
__device__ __half g_qh[NELEM], g_ql[NELEM];                  // q split (post-rope)
__device__ __half g_kh[NELEM], g_kl[NELEM];                  // k split (post-rope)
__device__ __half g_vh[NELEM], g_vl[NELEM];                  // v split
__device__ __half g_ah[NELEM], g_al[NELEM];                  // attn out split

// ===========================================================================
// helpers
// ===========================================================================
__device__ __forceinline__ uint32_t smem_u32(const void* p) {
    uint32_t a;
    asm("{ .reg .u64 t; cvta.to.shared.u64 t, %1; cvt.u32.u64 %0, t; }"
        : "=r"(a) : "l"(p));
    return a;
}
__device__ __forceinline__ void ldsm_x4(uint32_t* r, uint32_t addr) {
    asm volatile("ldmatrix.sync.aligned.m8n8.x4.shared.b16 {%0,%1,%2,%3}, [%4];"
                 : "=r"(r[0]), "=r"(r[1]), "=r"(r[2]), "=r"(r[3]) : "r"(addr));
}
__device__ __forceinline__ void ldsm_x2(uint32_t& r0, uint32_t& r1, uint32_t addr) {
    asm volatile("ldmatrix.sync.aligned.m8n8.x2.shared.b16 {%0,%1}, [%2];"
                 : "=r"(r0), "=r"(r1) : "r"(addr));
}
__device__ __forceinline__ void ldsm_x2t(uint32_t& r0, uint32_t& r1, uint32_t addr) {
    asm volatile("ldmatrix.sync.aligned.m8n8.x2.trans.shared.b16 {%0,%1}, [%2];"
                 : "=r"(r0), "=r"(r1) : "r"(addr));
}
__device__ __forceinline__ void mma16816(float* c,
    uint32_t a0, uint32_t a1, uint32_t a2, uint32_t a3, uint32_t b0, uint32_t b1) {
    asm volatile(
        "mma.sync.aligned.m16n8k16.row.col.f32.f16.f16.f32 "
        "{%0,%1,%2,%3}, {%4,%5,%6,%7}, {%8,%9}, {%0,%1,%2,%3};"
        : "+f"(c[0]), "+f"(c[1]), "+f"(c[2]), "+f"(c[3])
        : "r"(a0), "r"(a1), "r"(a2), "r"(a3), "r"(b0), "r"(b1));
}
__device__ __forceinline__ uint32_t pack_h2(float a, float b) {
    __half2 h = __floats2half2_rn(a, b);
    return *(uint32_t*)&h;
}
__device__ __forceinline__ void hsplit(float x, __half& h, __half& l) {
    h = __float2half_rn(x);
    l = __float2half_rn(x - __half2float(h));
}
#define CP_ASYNC16(dst, src) \
    asm volatile("cp.async.cg.shared.global [%0], [%1], 16;" :: "r"(dst), "l"(src))
#define CP_COMMIT() asm volatile("cp.async.commit_group;" ::: "memory")
#define CP_WAIT(n)  asm volatile("cp.async.wait_group %0;" :: "n"(n) : "memory")

// ===========================================================================
// split: fp32 -> (hi,lo) fp16 pairs
// ===========================================================================
__global__ __launch_bounds__(256) void split_kernel(
    const float* __restrict__ src, __half* __restrict__ hi,
    __half* __restrict__ lo, int n4)
{
    int i = blockIdx.x * blockDim.x + threadIdx.x;
    if (i >= n4) return;
    float4 v = ((const float4*)src)[i];
    __half h0,h1,h2,h3,l0,l1,l2,l3;
    hsplit(v.x,h0,l0); hsplit(v.y,h1,l1); hsplit(v.z,h2,l2); hsplit(v.w,h3,l3);
    ((__half2*)hi)[2*i]   = __halves2half2(h0,h1);
    ((__half2*)hi)[2*i+1] = __halves2half2(h2,h3);
    ((__half2*)lo)[2*i]   = __halves2half2(l0,l1);
    ((__half2*)lo)[2*i+1] = __halves2half2(l2,l3);
}

// ===========================================================================
// GEMM fp16x3, cp.async double-buffered.
// C[4096,1024] = A @ B^T + bias ; A,B pre-split halves (ld=1024).
// CTA 128x128, 8 warps (4Mx2N), k-chunk 32, 2 stages.
// mode 0: flat fp32   mode 1: head-major fp32   mode 2: head-major fp32+halves
// ===========================================================================
#define GSTR 40
#define GARR (128*GSTR)                 // halves per array
#define GEMM_SMEM (2*4*GARR*2)          // 81920 B

__global__ __launch_bounds__(256) void gemm_mma2(
    const __half* __restrict__ Ah, const __half* __restrict__ Al,
    const __half* __restrict__ Bh, const __half* __restrict__ Bl,
    const float* __restrict__ bias, float* __restrict__ C,
    __half* __restrict__ Ch, __half* __restrict__ Cl, int mode)
{
    extern __shared__ __half gsm[];
    const uint32_t gb = smem_u32(gsm);
    const int tid  = threadIdx.x;
    const int lane = tid & 31;
    const int warp = tid >> 5;
    const int wm = warp >> 1, wn = warp & 1;
    const int l4 = lane & 15;
    const int m0 = blockIdx.y * 128;
    const int n0 = blockIdx.x * 128;

    // fill stage s with k-offset kt (in halves)
    auto fill = [&](int s, int kt) {
#pragma unroll
        for (int e = 0; e < 4; e++) {               // A: Ah,Al
            int cid = tid + e * 256;                // 0..1023
            int a = cid >> 9, r = (cid >> 2) & 127, qq = cid & 3;
            const __half* src = (a ? Al : Ah) + (size_t)(m0 + r) * 1024 + kt + qq * 8;
            uint32_t dst = gb + (uint32_t)((s*4 + a) * GARR + r * GSTR + qq * 8) * 2;
            CP_ASYNC16(dst, src);
        }
#pragma unroll
        for (int e = 0; e < 4; e++) {               // B: Bh,Bl
            int cid = tid + e * 256;
            int a = cid >> 9, r = (cid >> 2) & 127, qq = cid & 3;
            const __half* src = (a ? Bl : Bh) + (size_t)(n0 + r) * 1024 + kt + qq * 8;
            uint32_t dst = gb + (uint32_t)((s*4 + 2 + a) * GARR + r * GSTR + qq * 8) * 2;
            CP_ASYNC16(dst, src);
        }
    };

    float acc[2][8][4];
#pragma unroll
    for (int i = 0; i < 2; i++)
#pragma unroll
        for (int j = 0; j < 8; j++)
#pragma unroll
            for (int c = 0; c < 4; c++) acc[i][j][c] = 0.f;

    fill(0, 0);  CP_COMMIT();
    fill(1, 32); CP_COMMIT();

    for (int c = 0; c < 32; c++) {
        const int s = c & 1;
        if (c < 31) { CP_WAIT(1); } else { CP_WAIT(0); }
        __syncthreads();

        const uint32_t ah_b = gb + (uint32_t)(s*4 + 0) * GARR * 2;
        const uint32_t al_b = gb + (uint32_t)(s*4 + 1) * GARR * 2;
        const uint32_t bh_b = gb + (uint32_t)(s*4 + 2) * GARR * 2;
        const uint32_t bl_b = gb + (uint32_t)(s*4 + 3) * GARR * 2;

#pragma unroll
        for (int ks = 0; ks < 2; ks++) {
            uint32_t afh[2][4], afl[2][4];
#pragma unroll
            for (int mt = 0; mt < 2; mt++) {
                uint32_t off = (uint32_t)((wm*32 + mt*16 + (lane & 15)) * GSTR
                                          + ks*16 + (lane >> 4) * 8) * 2;
                ldsm_x4(afh[mt], ah_b + off);
                ldsm_x4(afl[mt], al_b + off);
            }
#pragma unroll
            for (int nt = 0; nt < 8; nt++) {
                uint32_t off = (uint32_t)((wn*64 + nt*8 + (l4 & 7)) * GSTR
                                          + ks*16 + (l4 >> 3) * 8) * 2;
                uint32_t b0h, b1h, b0l, b1l;
                ldsm_x2(b0h, b1h, bh_b + off);
                ldsm_x2(b0l, b1l, bl_b + off);
#pragma unroll
                for (int mt = 0; mt < 2; mt++) {
                    mma16816(acc[mt][nt], afh[mt][0], afh[mt][1], afh[mt][2], afh[mt][3], b0h, b1h);
                    mma16816(acc[mt][nt], afh[mt][0], afh[mt][1], afh[mt][2], afh[mt][3], b0l, b1l);
                    mma16816(acc[mt][nt], afl[mt][0], afl[mt][1], afl[mt][2], afl[mt][3], b0h, b1h);
                }
            }
        }
        __syncthreads();
        if (c + 2 < 32) { fill(s, (c + 2) * 32); CP_COMMIT(); }
    }

    // epilogue
#pragma unroll
    for (int mt = 0; mt < 2; mt++) {
        int r_lo = m0 + wm*32 + mt*16 + (lane >> 2);
        int r_hi = r_lo + 8;
#pragma unroll
        for (int nt = 0; nt < 8; nt++) {
            int col = n0 + wn*64 + nt*8 + (lane & 3) * 2;
            float bx = bias[col], by = bias[col + 1];
            float2 lo = make_float2(acc[mt][nt][0] + bx, acc[mt][nt][1] + by);
            float2 hi = make_float2(acc[mt][nt][2] + bx, acc[mt][nt][3] + by);
            if (mode == 0) {
                *(float2*)&C[(size_t)r_lo * 1024 + col] = lo;
                *(float2*)&C[(size_t)r_hi * 1024 + col] = hi;
            } else {
                int h = col >> 6, d = col & 63;
                int b_lo = r_lo >> 11, l_lo = r_lo & 2047;
                int b_hi = r_hi >> 11, l_hi = r_hi & 2047;
                size_t i_lo = (size_t)((b_lo*N_HEADS + h)*SEQ_L + l_lo)*HEAD_DIM + d;
                size_t i_hi = (size_t)((b_hi*N_HEADS + h)*SEQ_L + l_hi)*HEAD_DIM + d;
                *(float2*)&C[i_lo] = lo;
                *(float2*)&C[i_hi] = hi;
                if (mode == 2) {
                    __half hh, hl;
                    __half h0,h1,l0,l1;
                    hsplit(lo.x, h0, l0); hsplit(lo.y, h1, l1);
                    *(__half2*)&Ch[i_lo] = __halves2half2(h0, h1);
                    *(__half2*)&Cl[i_lo] = __halves2half2(l0, l1);
                    hsplit(hi.x, h0, l0); hsplit(hi.y, h1, l1);
                    *(__half2*)&Ch[i_hi] = __halves2half2(h0, h1);
                    *(__half2*)&Cl[i_hi] = __halves2half2(l0, l1);
                    (void)hh; (void)hl;
                }
            }
        }
    }
}

// ===========================================================================
// RoPE: q fp32 -> q halves; k fp32 -> k fp32 (in place, required output) + halves
// ===========================================================================
__global__ __launch_bounds__(256) void rope_kernel(
    const float* __restrict__ q, float* __restrict__ k,
    __half* __restrict__ qh, __half* __restrict__ ql,
    __half* __restrict__ kh, __half* __restrict__ kl,
    const int* __restrict__ dt)
{
    int idx = blockIdx.x * blockDim.x + threadIdx.x;
    int i  = idx & 31;
    int l  = (idx >> 5) & (SEQ_L-1);
    int bh = idx >> 16;
    float t = (float)dt[l >> 7];
    float ang = t * __expf(-(float)i * (11.512925464970229f / 32.0f));
    float s, c;
    __sincosf(ang, &s, &c);
    size_t base = (size_t)(bh*SEQ_L + l)*HEAD_DIM + i;

    float q0 = q[base], q1 = q[base+32];
    float qr0 = q0*c - q1*s, qr1 = q1*c + q0*s;
    __half hh, hl;
    hsplit(qr0, hh, hl); qh[base]    = hh; ql[base]    = hl;
    hsplit(qr1, hh, hl); qh[base+32] = hh; ql[base+32] = hl;

    float k0 = k[base], k1 = k[base+32];
    float kr0 = k0*c - k1*s, kr1 = k1*c + k0*s;
    k[base] = kr0; k[base+32] = kr1;
    hsplit(kr0, hh, hl); kh[base]    = hh; kl[base]    = hl;
    hsplit(kr1, hh, hl); kh[base+32] = hh; kl[base+32] = hl;
}

// ===========================================================================
// Flash attention fp16x3, M=128 q-rows, 8 warps, Tk=64, cp.async 2-stage KV.
// Inputs pre-split halves (head-major). Output: half pairs, flat (b,l,h*64+d).
// ===========================================================================
#define FSTR 72
#define FQ   (128*FSTR)
#define FK   (64*FSTR)
#define FLASH_SMEM ((2*FQ + 8*FK)*2)    // 110592 B

__global__ __launch_bounds__(256) void flash_mma(
    const __half* __restrict__ qh, const __half* __restrict__ ql,
    const __half* __restrict__ kh, const __half* __restrict__ kl,
    const __half* __restrict__ vh, const __half* __restrict__ vl,
    __half* __restrict__ oh, __half* __restrict__ ol)
{
    extern __shared__ __half fsm[];
    const uint32_t fb = smem_u32(fsm);
    const int tid  = threadIdx.x;
    const int lane = tid & 31;
    const int warp = tid >> 5;
    const int l4   = lane & 15;
    const int b = blockIdx.z, h = blockIdx.y;
    const int qbase = blockIdx.x * 128;
    const size_t bh_off = (size_t)(b*N_HEADS + h)*KV_STRIDE;

    const __half* kv_src[4] = { kh + bh_off, kl + bh_off, vh + bh_off, vl + bh_off };

    // Q fill (2 arrays x 128 rows x 8 chunks = 2048 chunks)
#pragma unroll
    for (int e = 0; e < 8; e++) {
        int cid = tid + e * 256;
        int a = cid >> 10, r = (cid >> 3) & 127, qq = cid & 7;
        const __half* src = (a ? ql : qh) + bh_off + (size_t)(qbase + r) * 64 + qq * 8;
        uint32_t dst = fb + (uint32_t)(a*FQ + r*FSTR + qq*8) * 2;
        CP_ASYNC16(dst, src);
    }
    CP_COMMIT();

    auto fillKV = [&](int s, int kt) {
#pragma unroll
        for (int e = 0; e < 8; e++) {
            int cid = tid + e * 256;
            int a = cid >> 9, r = (cid >> 3) & 63, qq = cid & 7;
            const __half* src = kv_src[a] + (size_t)(kt + r) * 64 + qq * 8;
            uint32_t dst = fb + (uint32_t)(2*FQ + (s*4 + a)*FK + r*FSTR + qq*8) * 2;
            CP_ASYNC16(dst, src);
        }
    };
    fillKV(0, 0);  CP_COMMIT();
    fillKV(1, 64); CP_COMMIT();

    CP_WAIT(2);              // Q ready
    __syncthreads();

    // hoist Q fragments
    uint32_t qfh[4][4], qfl[4][4];
#pragma unroll
    for (int s = 0; s < 4; s++) {
        uint32_t off = (uint32_t)((warp*16 + (lane & 15)) * FSTR
                                  + s*16 + (lane >> 4) * 8) * 2;
        ldsm_x4(qfh[s], fb + off);
        ldsm_x4(qfl[s], fb + (uint32_t)FQ*2 + off);
    }

    float oacc[8][4];
#pragma unroll
    for (int n = 0; n < 8; n++)
#pragma unroll
        for (int c = 0; c < 4; c++) oacc[n][c] = 0.f;
    float m_lo = -1e30f, m_hi = -1e30f;
    float l_lo = 0.f, l_hi = 0.f;
    const float scale = 0.125f;

    for (int c = 0; c < 32; c++) {
        const int s = c & 1;
        if (c < 31) { CP_WAIT(1); } else { CP_WAIT(0); }
        __syncthreads();

        const uint32_t kh_b = fb + (uint32_t)(2*FQ + (s*4 + 0)*FK) * 2;
        const uint32_t kl_b = fb + (uint32_t)(2*FQ + (s*4 + 1)*FK) * 2;
        const uint32_t vh_b = fb + (uint32_t)(2*FQ + (s*4 + 2)*FK) * 2;
        const uint32_t vl_b = fb + (uint32_t)(2*FQ + (s*4 + 3)*FK) * 2;

        // S = Q K^T
        float sacc[8][4];
#pragma unroll
        for (int j = 0; j < 8; j++)
#pragma unroll
            for (int cc = 0; cc < 4; cc++) sacc[j][cc] = 0.f;
#pragma unroll
        for (int j = 0; j < 8; j++) {
#pragma unroll
            for (int ks = 0; ks < 4; ks++) {
                uint32_t off = (uint32_t)((j*8 + (l4 & 7)) * FSTR
                                          + ks*16 + (l4 >> 3) * 8) * 2;
                uint32_t b0h, b1h, b0l, b1l;
                ldsm_x2(b0h, b1h, kh_b + off);
                ldsm_x2(b0l, b1l, kl_b + off);
                mma16816(sacc[j], qfh[ks][0], qfh[ks][1], qfh[ks][2], qfh[ks][3], b0h, b1h);
                mma16816(sacc[j], qfh[ks][0], qfh[ks][1], qfh[ks][2], qfh[ks][3], b0l, b1l);
                mma16816(sacc[j], qfl[ks][0], qfl[ks][1], qfl[ks][2], qfl[ks][3], b0h, b1h);
            }
        }

        // online softmax
        float mx0 = -1e30f, mx1 = -1e30f;
#pragma unroll
        for (int j = 0; j < 8; j++) {
            mx0 = fmaxf(mx0, fmaxf(sacc[j][0], sacc[j][1]));
            mx1 = fmaxf(mx1, fmaxf(sacc[j][2], sacc[j][3]));
        }
        mx0 = fmaxf(mx0, __shfl_xor_sync(0xffffffffu, mx0, 1));
        mx0 = fmaxf(mx0, __shfl_xor_sync(0xffffffffu, mx0, 2));
        mx1 = fmaxf(mx1, __shfl_xor_sync(0xffffffffu, mx1, 1));
        mx1 = fmaxf(mx1, __shfl_xor_sync(0xffffffffu, mx1, 2));
        float mn0 = fmaxf(m_lo, mx0 * scale);
        float mn1 = fmaxf(m_hi, mx1 * scale);
        float al0 = __expf(m_lo - mn0);
        float al1 = __expf(m_hi - mn1);
        m_lo = mn0; m_hi = mn1;
        float sum0 = 0.f, sum1 = 0.f;
#pragma unroll
        for (int j = 0; j < 8; j++) {
            sacc[j][0] = __expf(sacc[j][0] * scale - mn0);
            sacc[j][1] = __expf(sacc[j][1] * scale - mn0);
            sacc[j][2] = __expf(sacc[j][2] * scale - mn1);
            sacc[j][3] = __expf(sacc[j][3] * scale - mn1);
            sum0 += sacc[j][0] + sacc[j][1];
            sum1 += sacc[j][2] + sacc[j][3];
        }
        sum0 += __shfl_xor_sync(0xffffffffu, sum0, 1);
        sum0 += __shfl_xor_sync(0xffffffffu, sum0, 2);
        sum1 += __shfl_xor_sync(0xffffffffu, sum1, 1);
        sum1 += __shfl_xor_sync(0xffffffffu, sum1, 2);
        l_lo = l_lo * al0 + sum0;
        l_hi = l_hi * al1 + sum1;
#pragma unroll
        for (int n = 0; n < 8; n++) {
            oacc[n][0] *= al0; oacc[n][1] *= al0;
            oacc[n][2] *= al1; oacc[n][3] *= al1;
        }

        // PV
#pragma unroll
        for (int t = 0; t < 4; t++) {
            uint32_t a0 = pack_h2(sacc[2*t][0],   sacc[2*t][1]);
            uint32_t a1 = pack_h2(sacc[2*t][2],   sacc[2*t][3]);
            uint32_t a2 = pack_h2(sacc[2*t+1][0], sacc[2*t+1][1]);
            uint32_t a3 = pack_h2(sacc[2*t+1][2], sacc[2*t+1][3]);
#pragma unroll
            for (int n = 0; n < 8; n++) {
                uint32_t off = (uint32_t)((t*16 + (l4 & 7) + (l4 >> 3) * 8) * FSTR
                                          + n*8) * 2;
                uint32_t b0, b1;
                ldsm_x2t(b0, b1, vh_b + off);
                mma16816(oacc[n], a0, a1, a2, a3, b0, b1);
                ldsm_x2t(b0, b1, vl_b + off);
                mma16816(oacc[n], a0, a1, a2, a3, b0, b1);
            }
        }

        __syncthreads();
        if (c + 2 < 32) { fillKV(s, (c + 2) * 64); CP_COMMIT(); }
    }

    // normalize + write half pairs (flat (b, l, h*64+d))
    float inv0 = 1.0f / l_lo;
    float inv1 = 1.0f / l_hi;
    int r_lo = qbase + warp*16 + (lane >> 2);
    int r_hi = r_lo + 8;
#pragma unroll
    for (int n = 0; n < 8; n++) {
        int col = h*HEAD_DIM + n*8 + (lane & 3)*2;
        size_t i_lo = (size_t)(b*SEQ_L + r_lo)*D_MODEL + col;
        size_t i_hi = (size_t)(b*SEQ_L + r_hi)*D_MODEL + col;
        __half h0,h1,l0,l1;
        hsplit(oacc[n][0]*inv0, h0, l0); hsplit(oacc[n][1]*inv0, h1, l1);
        *(__half2*)&oh[i_lo] = __halves2half2(h0, h1);
        *(__half2*)&ol[i_lo] = __halves2half2(l0, l1);
        hsplit(oacc[n][2]*inv1, h0, l0); hsplit(oacc[n][3]*inv1, h1, l1);
        *(__half2*)&oh[i_hi] = __halves2half2(h0, h1);
        *(__half2*)&ol[i_hi] = __halves2half2(l0, l1);
    }
}

// ---------------------------------------------------------------------------
extern "C" void kernel_launch(void* const* d_in, const int* in_sizes, int n_in,
                              void* d_out, int out_size)
{
    const float* x  = (const float*)d_in[0];
    const int*   dt = (const int*)  d_in[1];
    const float* Wq = (const float*)d_in[2];
    const float* bq = (const float*)d_in[3];
    const float* Wk = (const float*)d_in[4];
    const float* bk = (const float*)d_in[5];
    const float* Wv = (const float*)d_in[6];
    const float* bv = (const float*)d_in[7];
    const float* Wo = (const float*)d_in[8];
    const float* bo = (const float*)d_in[9];

    float* outp  = (float*)d_out;
    float* k_out = outp  + NELEM;
    float* v_out = k_out + NELEM;

    float *qbuf;
    __half *xh,*xl,*wh,*wl,*qh,*ql,*kh,*kl,*vh,*vl,*ah,*al;
    cudaGetSymbolAddress((void**)&qbuf, g_q);
    cudaGetSymbolAddress((void**)&xh, g_xh); cudaGetSymbolAddress((void**)&xl, g_xl);
    cudaGetSymbolAddress((void**)&wh, g_wh); cudaGetSymbolAddress((void**)&wl, g_wl);
    cudaGetSymbolAddress((void**)&qh, g_qh); cudaGetSymbolAddress((void**)&ql, g_ql);
    cudaGetSymbolAddress((void**)&kh, g_kh); cudaGetSymbolAddress((void**)&kl, g_kl);
    cudaGetSymbolAddress((void**)&vh, g_vh); cudaGetSymbolAddress((void**)&vl, g_vl);
    cudaGetSymbolAddress((void**)&ah, g_ah); cudaGetSymbolAddress((void**)&al, g_al);

    cudaFuncSetAttribute(gemm_mma2, cudaFuncAttributeMaxDynamicSharedMemorySize, GEMM_SMEM);
    cudaFuncSetAttribute(flash_mma, cudaFuncAttributeMaxDynamicSharedMemorySize, FLASH_SMEM);

    const int WSZ = 1024*1024;
    // splits
    split_kernel<<<4096, 256>>>(x,  xh, xl, (int)(NELEM/4));
    split_kernel<<<1024, 256>>>(Wq, wh + 0*WSZ, wl + 0*WSZ, WSZ/4);
    split_kernel<<<1024, 256>>>(Wk, wh + 1*WSZ, wl + 1*WSZ, WSZ/4);
    split_kernel<<<1024, 256>>>(Wv, wh + 2*WSZ, wl + 2*WSZ, WSZ/4);
    split_kernel<<<1024, 256>>>(Wo, wh + 3*WSZ, wl + 3*WSZ, WSZ/4);

    dim3 ggrid(8, 32);
    // projections
    gemm_mma2<<<ggrid, 256, GEMM_SMEM>>>(xh, xl, wh+0*WSZ, wl+0*WSZ, bq, qbuf,  nullptr, nullptr, 1);
    gemm_mma2<<<ggrid, 256, GEMM_SMEM>>>(xh, xl, wh+1*WSZ, wl+1*WSZ, bk, k_out, nullptr, nullptr, 1);
    gemm_mma2<<<ggrid, 256, GEMM_SMEM>>>(xh, xl, wh+2*WSZ, wl+2*WSZ, bv, v_out, vh, vl, 2);

    rope_kernel<<<8192, 256>>>(qbuf, k_out, qh, ql, kh, kl, dt);

    flash_mma<<<dim3(SEQ_L/128, N_HEADS, BATCH), 256, FLASH_SMEM>>>(
        qh, ql, kh, kl, vh, vl, ah, al);

    gemm_mma2<<<ggrid, 256, GEMM_SMEM>>>(ah, al, wh+3*WSZ, wl+3*WSZ, bo, outp, nullptr, nullptr, 0);
}

// round 5
// speedup vs baseline: 3.9460x; 1.2959x over previous
#include <cuda_runtime.h>
#include <cuda_fp16.h>
#include <cstdint>

#define D_MODEL   1024
#define N_HEADS   16
#define HEAD_DIM  64
#define SEQ_L     2048
#define BATCH     2
#define BL        (BATCH*SEQ_L)
#define KV_STRIDE (SEQ_L*HEAD_DIM)
#define NELEM     ((size_t)BL*D_MODEL)   // 4M

// static scratch (allocation-free)
__device__ float  g_q [BATCH*N_HEADS*SEQ_L*HEAD_DIM];        // q fp32 (pre-rope)
__device__ __half g_xh[NELEM];                               // x rounded to fp16
__device__ __half g_wh[4][1024*1024], g_wl[4][1024*1024];    // W hi/lo
__device__ __half g_qh[NELEM];                               // q fp16 (post-rope)
__device__ __half g_kh[NELEM], g_kl[NELEM];                  // k hi/lo (post-rope)
__device__ __half g_vh[NELEM], g_vl[NELEM];                  // v hi/lo
__device__ __half g_ah[NELEM];                               // attn out fp16

// ===========================================================================
// helpers
// ===========================================================================
__device__ __forceinline__ uint32_t smem_u32(const void* p) {
    uint32_t a;
    asm("{ .reg .u64 t; cvta.to.shared.u64 t, %1; cvt.u32.u64 %0, t; }"
        : "=r"(a) : "l"(p));
    return a;
}
__device__ __forceinline__ void ldsm_x4(uint32_t* r, uint32_t addr) {
    asm volatile("ldmatrix.sync.aligned.m8n8.x4.shared.b16 {%0,%1,%2,%3}, [%4];"
                 : "=r"(r[0]), "=r"(r[1]), "=r"(r[2]), "=r"(r[3]) : "r"(addr));
}
__device__ __forceinline__ void ldsm_x2(uint32_t& r0, uint32_t& r1, uint32_t addr) {
    asm volatile("ldmatrix.sync.aligned.m8n8.x2.shared.b16 {%0,%1}, [%2];"
                 : "=r"(r0), "=r"(r1) : "r"(addr));
}
__device__ __forceinline__ void ldsm_x2t(uint32_t& r0, uint32_t& r1, uint32_t addr) {
    asm volatile("ldmatrix.sync.aligned.m8n8.x2.trans.shared.b16 {%0,%1}, [%2];"
                 : "=r"(r0), "=r"(r1) : "r"(addr));
}
__device__ __forceinline__ void mma16816(float* c,
    uint32_t a0, uint32_t a1, uint32_t a2, uint32_t a3, uint32_t b0, uint32_t b1) {
    asm volatile(
        "mma.sync.aligned.m16n8k16.row.col.f32.f16.f16.f32 "
        "{%0,%1,%2,%3}, {%4,%5,%6,%7}, {%8,%9}, {%0,%1,%2,%3};"
        : "+f"(c[0]), "+f"(c[1]), "+f"(c[2]), "+f"(c[3])
        : "r"(a0), "r"(a1), "r"(a2), "r"(a3), "r"(b0), "r"(b1));
}
__device__ __forceinline__ uint32_t pack_h2(float a, float b) {
    __half2 h = __floats2half2_rn(a, b);
    return *(uint32_t*)&h;
}
__device__ __forceinline__ void hsplit(float x, __half& h, __half& l) {
    h = __float2half_rn(x);
    l = __float2half_rn(x - __half2float(h));
}
#define CP_ASYNC16(dst, src) \
    asm volatile("cp.async.cg.shared.global [%0], [%1], 16;" :: "r"(dst), "l"(src))
#define CP_COMMIT() asm volatile("cp.async.commit_group;" ::: "memory")
#define CP_WAIT(n)  asm volatile("cp.async.wait_group %0;" :: "n"(n) : "memory")

// ===========================================================================
// splits
// ===========================================================================
__global__ __launch_bounds__(256) void split_hi_kernel(
    const float* __restrict__ src, __half* __restrict__ hi, int n4)
{
    int i = blockIdx.x * blockDim.x + threadIdx.x;
    if (i >= n4) return;
    float4 v = ((const float4*)src)[i];
    ((__half2*)hi)[2*i]   = __floats2half2_rn(v.x, v.y);
    ((__half2*)hi)[2*i+1] = __floats2half2_rn(v.z, v.w);
}

// all four weight matrices in one launch: n4 per matrix = 1M/4
__global__ __launch_bounds__(256) void split4_kernel(
    const float* __restrict__ w0, const float* __restrict__ w1,
    const float* __restrict__ w2, const float* __restrict__ w3,
    __half* __restrict__ hi, __half* __restrict__ lo)
{
    int i = blockIdx.x * blockDim.x + threadIdx.x;   // 0 .. 4*262144-1
    int m = i >> 18;
    int j = i & 262143;
    const float* src = (m == 0) ? w0 : (m == 1) ? w1 : (m == 2) ? w2 : w3;
    float4 v = ((const float4*)src)[j];
    __half h0,h1,h2,h3,l0,l1,l2,l3;
    hsplit(v.x,h0,l0); hsplit(v.y,h1,l1); hsplit(v.z,h2,l2); hsplit(v.w,h3,l3);
    size_t o = (size_t)m * 262144 + j;
    ((__half2*)hi)[2*o]   = __halves2half2(h0,h1);
    ((__half2*)hi)[2*o+1] = __halves2half2(h2,h3);
    ((__half2*)lo)[2*o]   = __halves2half2(l0,l1);
    ((__half2*)lo)[2*o+1] = __halves2half2(l2,l3);
}

// ===========================================================================
// GEMM fp16x2 (A fp16-rounded, B = Bh+Bl): C = A @ B^T + bias
// CTA 128x128, 8 warps (4Mx2N), k-chunk 32, 2-stage cp.async, 2 CTA/SM.
// mode 0: flat fp32   mode 1: head-major fp32   mode 2: head-major fp32+halves
// ===========================================================================
#define GSTR 40
#define GARR (128*GSTR)                 // halves per array
#define GEMM_SMEM (2*3*GARR*2)          // 61440 B

__global__ __launch_bounds__(256, 2) void gemm_mma2(
    const __half* __restrict__ Ah,
    const __half* __restrict__ Bh, const __half* __restrict__ Bl,
    const float* __restrict__ bias, float* __restrict__ C,
    __half* __restrict__ Ch, __half* __restrict__ Cl, int mode)
{
    extern __shared__ __half gsm[];
    const uint32_t gb = smem_u32(gsm);
    const int tid  = threadIdx.x;
    const int lane = tid & 31;
    const int warp = tid >> 5;
    const int wm = warp >> 1, wn = warp & 1;
    const int l4 = lane & 15;
    const int m0 = blockIdx.y * 128;
    const int n0 = blockIdx.x * 128;

    auto fill = [&](int s, int kt) {
#pragma unroll
        for (int e = 0; e < 2; e++) {               // A hi
            int cid = tid + e * 256;                // 0..511
            int r = cid >> 2, qq = cid & 3;
            const __half* src = Ah + (size_t)(m0 + r) * 1024 + kt + qq * 8;
            uint32_t dst = gb + (uint32_t)((s*3) * GARR + r * GSTR + qq * 8) * 2;
            CP_ASYNC16(dst, src);
        }
#pragma unroll
        for (int e = 0; e < 4; e++) {               // B hi/lo
            int cid = tid + e * 256;                // 0..1023
            int a = cid >> 9, r = (cid >> 2) & 127, qq = cid & 3;
            const __half* src = (a ? Bl : Bh) + (size_t)(n0 + r) * 1024 + kt + qq * 8;
            uint32_t dst = gb + (uint32_t)((s*3 + 1 + a) * GARR + r * GSTR + qq * 8) * 2;
            CP_ASYNC16(dst, src);
        }
    };

    float acc[2][8][4];
#pragma unroll
    for (int i = 0; i < 2; i++)
#pragma unroll
        for (int j = 0; j < 8; j++)
#pragma unroll
            for (int c = 0; c < 4; c++) acc[i][j][c] = 0.f;

    fill(0, 0);  CP_COMMIT();
    fill(1, 32); CP_COMMIT();

    for (int c = 0; c < 32; c++) {
        const int s = c & 1;
        if (c < 31) { CP_WAIT(1); } else { CP_WAIT(0); }
        __syncthreads();

        const uint32_t ah_b = gb + (uint32_t)(s*3 + 0) * GARR * 2;
        const uint32_t bh_b = gb + (uint32_t)(s*3 + 1) * GARR * 2;
        const uint32_t bl_b = gb + (uint32_t)(s*3 + 2) * GARR * 2;

#pragma unroll
        for (int ks = 0; ks < 2; ks++) {
            uint32_t afh[2][4];
#pragma unroll
            for (int mt = 0; mt < 2; mt++) {
                uint32_t off = (uint32_t)((wm*32 + mt*16 + (lane & 15)) * GSTR
                                          + ks*16 + (lane >> 4) * 8) * 2;
                ldsm_x4(afh[mt], ah_b + off);
            }
#pragma unroll
            for (int nt = 0; nt < 8; nt++) {
                uint32_t off = (uint32_t)((wn*64 + nt*8 + (l4 & 7)) * GSTR
                                          + ks*16 + (l4 >> 3) * 8) * 2;
                uint32_t b0h, b1h, b0l, b1l;
                ldsm_x2(b0h, b1h, bh_b + off);
                ldsm_x2(b0l, b1l, bl_b + off);
#pragma unroll
                for (int mt = 0; mt < 2; mt++) {
                    mma16816(acc[mt][nt], afh[mt][0], afh[mt][1], afh[mt][2], afh[mt][3], b0h, b1h);
                    mma16816(acc[mt][nt], afh[mt][0], afh[mt][1], afh[mt][2], afh[mt][3], b0l, b1l);
                }
            }
        }
        __syncthreads();
        if (c + 2 < 32) { fill(s, (c + 2) * 32); CP_COMMIT(); }
    }

    // epilogue
#pragma unroll
    for (int mt = 0; mt < 2; mt++) {
        int r_lo = m0 + wm*32 + mt*16 + (lane >> 2);
        int r_hi = r_lo + 8;
#pragma unroll
        for (int nt = 0; nt < 8; nt++) {
            int col = n0 + wn*64 + nt*8 + (lane & 3) * 2;
            float bx = bias[col], by = bias[col + 1];
            float2 lo = make_float2(acc[mt][nt][0] + bx, acc[mt][nt][1] + by);
            float2 hi = make_float2(acc[mt][nt][2] + bx, acc[mt][nt][3] + by);
            if (mode == 0) {
                *(float2*)&C[(size_t)r_lo * 1024 + col] = lo;
                *(float2*)&C[(size_t)r_hi * 1024 + col] = hi;
            } else {
                int h = col >> 6, d = col & 63;
                int b_lo = r_lo >> 11, l_lo = r_lo & 2047;
                int b_hi = r_hi >> 11, l_hi = r_hi & 2047;
                size_t i_lo = (size_t)((b_lo*N_HEADS + h)*SEQ_L + l_lo)*HEAD_DIM + d;
                size_t i_hi = (size_t)((b_hi*N_HEADS + h)*SEQ_L + l_hi)*HEAD_DIM + d;
                *(float2*)&C[i_lo] = lo;
                *(float2*)&C[i_hi] = hi;
                if (mode == 2) {
                    __half h0,h1,l0,l1;
                    hsplit(lo.x, h0, l0); hsplit(lo.y, h1, l1);
                    *(__half2*)&Ch[i_lo] = __halves2half2(h0, h1);
                    *(__half2*)&Cl[i_lo] = __halves2half2(l0, l1);
                    hsplit(hi.x, h0, l0); hsplit(hi.y, h1, l1);
                    *(__half2*)&Ch[i_hi] = __halves2half2(h0, h1);
                    *(__half2*)&Cl[i_hi] = __halves2half2(l0, l1);
                }
            }
        }
    }
}

// ===========================================================================
// RoPE: q fp32 -> qh fp16; k fp32 -> k fp32 (output) + kh/kl halves
// ===========================================================================
__global__ __launch_bounds__(256) void rope_kernel(
    const float* __restrict__ q, float* __restrict__ k,
    __half* __restrict__ qh,
    __half* __restrict__ kh, __half* __restrict__ kl,
    const int* __restrict__ dt)
{
    int idx = blockIdx.x * blockDim.x + threadIdx.x;
    int i  = idx & 31;
    int l  = (idx >> 5) & (SEQ_L-1);
    int bh = idx >> 16;
    float t = (float)dt[l >> 7];
    float ang = t * __expf(-(float)i * (11.512925464970229f / 32.0f));
    float s, c;
    __sincosf(ang, &s, &c);
    size_t base = (size_t)(bh*SEQ_L + l)*HEAD_DIM + i;

    float q0 = q[base], q1 = q[base+32];
    qh[base]    = __float2half_rn(q0*c - q1*s);
    qh[base+32] = __float2half_rn(q1*c + q0*s);

    float k0 = k[base], k1 = k[base+32];
    float kr0 = k0*c - k1*s, kr1 = k1*c + k0*s;
    k[base] = kr0; k[base+32] = kr1;
    __half hh, hl;
    hsplit(kr0, hh, hl); kh[base]    = hh; kl[base]    = hl;
    hsplit(kr1, hh, hl); kh[base+32] = hh; kl[base+32] = hl;
}

// ===========================================================================
// Flash attention fp16x2: S = Qh*(Kh+Kl), PV = P*(Vh+Vl).
// M=128 q-rows, 8 warps, Tk=64, 2-stage cp.async KV, 2 CTA/SM.
// Output: fp16, flat (b, l, h*64+d).
// ===========================================================================
#define FSTR 72
#define FQ   (128*FSTR)
#define FK   (64*FSTR)
#define FLASH_SMEM ((FQ + 8*FK)*2)    // 92160 B

__global__ __launch_bounds__(256, 2) void flash_mma(
    const __half* __restrict__ qh,
    const __half* __restrict__ kh, const __half* __restrict__ kl,
    const __half* __restrict__ vh, const __half* __restrict__ vl,
    __half* __restrict__ oh)
{
    extern __shared__ __half fsm[];
    const uint32_t fb = smem_u32(fsm);
    const int tid  = threadIdx.x;
    const int lane = tid & 31;
    const int warp = tid >> 5;
    const int l4   = lane & 15;
    const int b = blockIdx.z, h = blockIdx.y;
    const int qbase = blockIdx.x * 128;
    const size_t bh_off = (size_t)(b*N_HEADS + h)*KV_STRIDE;

    const __half* kv_src[4] = { kh + bh_off, kl + bh_off, vh + bh_off, vl + bh_off };

    // Q fill: 128 rows x 8 chunks
#pragma unroll
    for (int e = 0; e < 4; e++) {
        int cid = tid + e * 256;
        int r = cid >> 3, qq = cid & 7;
        const __half* src = qh + bh_off + (size_t)(qbase + r) * 64 + qq * 8;
        uint32_t dst = fb + (uint32_t)(r*FSTR + qq*8) * 2;
        CP_ASYNC16(dst, src);
    }
    CP_COMMIT();

    auto fillKV = [&](int s, int kt) {
#pragma unroll
        for (int e = 0; e < 8; e++) {
            int cid = tid + e * 256;
            int a = cid >> 9, r = (cid >> 3) & 63, qq = cid & 7;
            const __half* src = kv_src[a] + (size_t)(kt + r) * 64 + qq * 8;
            uint32_t dst = fb + (uint32_t)(FQ + (s*4 + a)*FK + r*FSTR + qq*8) * 2;
            CP_ASYNC16(dst, src);
        }
    };
    fillKV(0, 0);  CP_COMMIT();
    fillKV(1, 64); CP_COMMIT();

    CP_WAIT(2);              // Q ready
    __syncthreads();

    // hoist Q fragments
    uint32_t qfh[4][4];
#pragma unroll
    for (int s = 0; s < 4; s++) {
        uint32_t off = (uint32_t)((warp*16 + (lane & 15)) * FSTR
                                  + s*16 + (lane >> 4) * 8) * 2;
        ldsm_x4(qfh[s], fb + off);
    }

    float oacc[8][4];
#pragma unroll
    for (int n = 0; n < 8; n++)
#pragma unroll
        for (int c = 0; c < 4; c++) oacc[n][c] = 0.f;
    float m_lo = -1e30f, m_hi = -1e30f;
    float l_lo = 0.f, l_hi = 0.f;
    const float scale = 0.125f;

    for (int c = 0; c < 32; c++) {
        const int s = c & 1;
        if (c < 31) { CP_WAIT(1); } else { CP_WAIT(0); }
        __syncthreads();

        const uint32_t kh_b = fb + (uint32_t)(FQ + (s*4 + 0)*FK) * 2;
        const uint32_t kl_b = fb + (uint32_t)(FQ + (s*4 + 1)*FK) * 2;
        const uint32_t vh_b = fb + (uint32_t)(FQ + (s*4 + 2)*FK) * 2;
        const uint32_t vl_b = fb + (uint32_t)(FQ + (s*4 + 3)*FK) * 2;

        // S = Q K^T (Qh * (Kh + Kl))
        float sacc[8][4];
#pragma unroll
        for (int j = 0; j < 8; j++)
#pragma unroll
            for (int cc = 0; cc < 4; cc++) sacc[j][cc] = 0.f;
#pragma unroll
        for (int j = 0; j < 8; j++) {
#pragma unroll
            for (int ks = 0; ks < 4; ks++) {
                uint32_t off = (uint32_t)((j*8 + (l4 & 7)) * FSTR
                                          + ks*16 + (l4 >> 3) * 8) * 2;
                uint32_t b0h, b1h, b0l, b1l;
                ldsm_x2(b0h, b1h, kh_b + off);
                ldsm_x2(b0l, b1l, kl_b + off);
                mma16816(sacc[j], qfh[ks][0], qfh[ks][1], qfh[ks][2], qfh[ks][3], b0h, b1h);
                mma16816(sacc[j], qfh[ks][0], qfh[ks][1], qfh[ks][2], qfh[ks][3], b0l, b1l);
            }
        }

        // online softmax
        float mx0 = -1e30f, mx1 = -1e30f;
#pragma unroll
        for (int j = 0; j < 8; j++) {
            mx0 = fmaxf(mx0, fmaxf(sacc[j][0], sacc[j][1]));
            mx1 = fmaxf(mx1, fmaxf(sacc[j][2], sacc[j][3]));
        }
        mx0 = fmaxf(mx0, __shfl_xor_sync(0xffffffffu, mx0, 1));
        mx0 = fmaxf(mx0, __shfl_xor_sync(0xffffffffu, mx0, 2));
        mx1 = fmaxf(mx1, __shfl_xor_sync(0xffffffffu, mx1, 1));
        mx1 = fmaxf(mx1, __shfl_xor_sync(0xffffffffu, mx1, 2));
        float mn0 = fmaxf(m_lo, mx0 * scale);
        float mn1 = fmaxf(m_hi, mx1 * scale);
        float al0 = __expf(m_lo - mn0);
        float al1 = __expf(m_hi - mn1);
        m_lo = mn0; m_hi = mn1;
        float sum0 = 0.f, sum1 = 0.f;
#pragma unroll
        for (int j = 0; j < 8; j++) {
            sacc[j][0] = __expf(sacc[j][0] * scale - mn0);
            sacc[j][1] = __expf(sacc[j][1] * scale - mn0);
            sacc[j][2] = __expf(sacc[j][2] * scale - mn1);
            sacc[j][3] = __expf(sacc[j][3] * scale - mn1);
            sum0 += sacc[j][0] + sacc[j][1];
            sum1 += sacc[j][2] + sacc[j][3];
        }
        sum0 += __shfl_xor_sync(0xffffffffu, sum0, 1);
        sum0 += __shfl_xor_sync(0xffffffffu, sum0, 2);
        sum1 += __shfl_xor_sync(0xffffffffu, sum1, 1);
        sum1 += __shfl_xor_sync(0xffffffffu, sum1, 2);
        l_lo = l_lo * al0 + sum0;
        l_hi = l_hi * al1 + sum1;
#pragma unroll
        for (int n = 0; n < 8; n++) {
            oacc[n][0] *= al0; oacc[n][1] *= al0;
            oacc[n][2] *= al1; oacc[n][3] *= al1;
        }

        // PV: P (fp16) x (Vh + Vl)
#pragma unroll
        for (int t = 0; t < 4; t++) {
            uint32_t a0 = pack_h2(sacc[2*t][0],   sacc[2*t][1]);
            uint32_t a1 = pack_h2(sacc[2*t][2],   sacc[2*t][3]);
            uint32_t a2 = pack_h2(sacc[2*t+1][0], sacc[2*t+1][1]);
            uint32_t a3 = pack_h2(sacc[2*t+1][2], sacc[2*t+1][3]);
#pragma unroll
            for (int n = 0; n < 8; n++) {
                uint32_t off = (uint32_t)((t*16 + (l4 & 7) + (l4 >> 3) * 8) * FSTR
                                          + n*8) * 2;
                uint32_t b0, b1;
                ldsm_x2t(b0, b1, vh_b + off);
                mma16816(oacc[n], a0, a1, a2, a3, b0, b1);
                ldsm_x2t(b0, b1, vl_b + off);
                mma16816(oacc[n], a0, a1, a2, a3, b0, b1);
            }
        }

        __syncthreads();
        if (c + 2 < 32) { fillKV(s, (c + 2) * 64); CP_COMMIT(); }
    }

    // normalize + write fp16 (flat (b, l, h*64+d))
    float inv0 = 1.0f / l_lo;
    float inv1 = 1.0f / l_hi;
    int r_lo = qbase + warp*16 + (lane >> 2);
    int r_hi = r_lo + 8;
#pragma unroll
    for (int n = 0; n < 8; n++) {
        int col = h*HEAD_DIM + n*8 + (lane & 3)*2;
        size_t i_lo = (size_t)(b*SEQ_L + r_lo)*D_MODEL + col;
        size_t i_hi = (size_t)(b*SEQ_L + r_hi)*D_MODEL + col;
        *(__half2*)&oh[i_lo] = __floats2half2_rn(oacc[n][0]*inv0, oacc[n][1]*inv0);
        *(__half2*)&oh[i_hi] = __floats2half2_rn(oacc[n][2]*inv1, oacc[n][3]*inv1);
    }
}

// ---------------------------------------------------------------------------
extern "C" void kernel_launch(void* const* d_in, const int* in_sizes, int n_in,
                              void* d_out, int out_size)
{
    const float* x  = (const float*)d_in[0];
    const int*   dt = (const int*)  d_in[1];
    const float* Wq = (const float*)d_in[2];
    const float* bq = (const float*)d_in[3];
    const float* Wk = (const float*)d_in[4];
    const float* bk = (const float*)d_in[5];
    const float* Wv = (const float*)d_in[6];
    const float* bv = (const float*)d_in[7];
    const float* Wo = (const float*)d_in[8];
    const float* bo = (const float*)d_in[9];

    float* outp  = (float*)d_out;
    float* k_out = outp  + NELEM;
    float* v_out = k_out + NELEM;

    float *qbuf;
    __half *xh,*wh,*wl,*qh,*kh,*kl,*vh,*vl,*ah;
    cudaGetSymbolAddress((void**)&qbuf, g_q);
    cudaGetSymbolAddress((void**)&xh, g_xh);
    cudaGetSymbolAddress((void**)&wh, g_wh); cudaGetSymbolAddress((void**)&wl, g_wl);
    cudaGetSymbolAddress((void**)&qh, g_qh);
    cudaGetSymbolAddress((void**)&kh, g_kh); cudaGetSymbolAddress((void**)&kl, g_kl);
    cudaGetSymbolAddress((void**)&vh, g_vh); cudaGetSymbolAddress((void**)&vl, g_vl);
    cudaGetSymbolAddress((void**)&ah, g_ah);

    cudaFuncSetAttribute(gemm_mma2, cudaFuncAttributeMaxDynamicSharedMemorySize, GEMM_SMEM);
    cudaFuncSetAttribute(flash_mma, cudaFuncAttributeMaxDynamicSharedMemorySize, FLASH_SMEM);

    const int WSZ = 1024*1024;
    split_hi_kernel<<<4096, 256>>>(x, xh, (int)(NELEM/4));
    split4_kernel<<<4096, 256>>>(Wq, Wk, Wv, Wo, wh, wl);

    dim3 ggrid(8, 32);
    gemm_mma2<<<ggrid, 256, GEMM_SMEM>>>(xh, wh+0*WSZ, wl+0*WSZ, bq, qbuf,  nullptr, nullptr, 1);
    gemm_mma2<<<ggrid, 256, GEMM_SMEM>>>(xh, wh+1*WSZ, wl+1*WSZ, bk, k_out, nullptr, nullptr, 1);
    gemm_mma2<<<ggrid, 256, GEMM_SMEM>>>(xh, wh+2*WSZ, wl+2*WSZ, bv, v_out, vh, vl, 2);

    rope_kernel<<<8192, 256>>>(qbuf, k_out, qh, kh, kl, dt);

    flash_mma<<<dim3(SEQ_L/128, N_HEADS, BATCH), 256, FLASH_SMEM>>>(
        qh, kh, kl, vh, vl, ah);

    gemm_mma2<<<ggrid, 256, GEMM_SMEM>>>(ah, wh+3*WSZ, wl+3*WSZ, bo, outp, nullptr, nullptr, 0);
}

// round 6
// speedup vs baseline: 4.3777x; 1.1094x over previous
#include <cuda_runtime.h>
#include <cuda_fp16.h>
#include <cstdint>

#define D_MODEL   1024
#define N_HEADS   16
#define HEAD_DIM  64
#define SEQ_L     2048
#define BATCH     2
#define BL        (BATCH*SEQ_L)
#define KV_STRIDE (SEQ_L*HEAD_DIM)
#define NELEM     ((size_t)BL*D_MODEL)   // 4M

// static scratch (allocation-free)
__device__ float  g_q [BATCH*N_HEADS*SEQ_L*HEAD_DIM];        // q fp32 (pre-rope)
__device__ __half g_xh[NELEM];                               // x rounded to fp16
__device__ __half g_wh[4][1024*1024], g_wl[4][1024*1024];    // W hi/lo (contiguous)
__device__ __half g_qh[NELEM];                               // q fp16 (post-rope)
__device__ __half g_kh[NELEM], g_kl[NELEM];                  // k hi/lo (post-rope)
__device__ __half g_vh[NELEM], g_vl[NELEM];                  // v hi/lo
__device__ __half g_ah[NELEM];                               // attn out fp16

// ===========================================================================
// helpers
// ===========================================================================
__device__ __forceinline__ uint32_t smem_u32(const void* p) {
    uint32_t a;
    asm("{ .reg .u64 t; cvta.to.shared.u64 t, %1; cvt.u32.u64 %0, t; }"
        : "=r"(a) : "l"(p));
    return a;
}
__device__ __forceinline__ void ldsm_x4(uint32_t* r, uint32_t addr) {
    asm volatile("ldmatrix.sync.aligned.m8n8.x4.shared.b16 {%0,%1,%2,%3}, [%4];"
                 : "=r"(r[0]), "=r"(r[1]), "=r"(r[2]), "=r"(r[3]) : "r"(addr));
}
__device__ __forceinline__ void ldsm_x4t(uint32_t* r, uint32_t addr) {
    asm volatile("ldmatrix.sync.aligned.m8n8.x4.trans.shared.b16 {%0,%1,%2,%3}, [%4];"
                 : "=r"(r[0]), "=r"(r[1]), "=r"(r[2]), "=r"(r[3]) : "r"(addr));
}
__device__ __forceinline__ void mma16816(float* c,
    uint32_t a0, uint32_t a1, uint32_t a2, uint32_t a3, uint32_t b0, uint32_t b1) {
    asm volatile(
        "mma.sync.aligned.m16n8k16.row.col.f32.f16.f16.f32 "
        "{%0,%1,%2,%3}, {%4,%5,%6,%7}, {%8,%9}, {%0,%1,%2,%3};"
        : "+f"(c[0]), "+f"(c[1]), "+f"(c[2]), "+f"(c[3])
        : "r"(a0), "r"(a1), "r"(a2), "r"(a3), "r"(b0), "r"(b1));
}
__device__ __forceinline__ uint32_t pack_h2(float a, float b) {
    __half2 h = __floats2half2_rn(a, b);
    return *(uint32_t*)&h;
}
__device__ __forceinline__ void hsplit(float x, __half& h, __half& l) {
    h = __float2half_rn(x);
    l = __float2half_rn(x - __half2float(h));
}
#define CP_ASYNC16(dst, src) \
    asm volatile("cp.async.cg.shared.global [%0], [%1], 16;" :: "r"(dst), "l"(src))
#define CP_COMMIT() asm volatile("cp.async.commit_group;" ::: "memory")
#define CP_WAIT(n)  asm volatile("cp.async.wait_group %0;" :: "n"(n) : "memory")

// ===========================================================================
// splits
// ===========================================================================
__global__ __launch_bounds__(256) void split_hi_kernel(
    const float* __restrict__ src, __half* __restrict__ hi, int n4)
{
    int i = blockIdx.x * blockDim.x + threadIdx.x;
    if (i >= n4) return;
    float4 v = ((const float4*)src)[i];
    ((__half2*)hi)[2*i]   = __floats2half2_rn(v.x, v.y);
    ((__half2*)hi)[2*i+1] = __floats2half2_rn(v.z, v.w);
}

__global__ __launch_bounds__(256) void split4_kernel(
    const float* __restrict__ w0, const float* __restrict__ w1,
    const float* __restrict__ w2, const float* __restrict__ w3,
    __half* __restrict__ hi, __half* __restrict__ lo)
{
    int i = blockIdx.x * blockDim.x + threadIdx.x;   // 0 .. 4*262144-1
    int m = i >> 18;
    int j = i & 262143;
    const float* src = (m == 0) ? w0 : (m == 1) ? w1 : (m == 2) ? w2 : w3;
    float4 v = ((const float4*)src)[j];
    __half h0,h1,h2,h3,l0,l1,l2,l3;
    hsplit(v.x,h0,l0); hsplit(v.y,h1,l1); hsplit(v.z,h2,l2); hsplit(v.w,h3,l3);
    size_t o = (size_t)m * 262144 + j;
    ((__half2*)hi)[2*o]   = __halves2half2(h0,h1);
    ((__half2*)hi)[2*o+1] = __halves2half2(h2,h3);
    ((__half2*)lo)[2*o]   = __halves2half2(l0,l1);
    ((__half2*)lo)[2*o+1] = __halves2half2(l2,l3);
}

// ===========================================================================
// GEMM fp16x2, fused multi-matrix: C_mat = A @ W_mat^T + bias_mat
// grid.x = 8*nmat (n-tiles within matrix fastest), grid.y = 32 (m-tiles).
// CTA 128x128, 8 warps (4Mx2N), k-chunk 32, 3-buffer cp.async (distance 2),
// ONE barrier per chunk, ldsm x4 for B (n-tile pairs). 2 CTA/SM.
// per-matrix mode: 0 flat fp32, 1 head-major fp32, 2 head-major fp32 + halves
// ===========================================================================
#define GSTR 40
#define GARR (128*GSTR)                 // halves per array (5120)
#define GSTAGE (3*GARR)                 // halves per stage
#define GEMM_SMEM (3*GSTAGE*2)          // 92160 B

struct GemmOut {
    const float* b0; const float* b1; const float* b2;
    float* C0; float* C1; float* C2;
    __half* Ch; __half* Cl;             // halves output (mode 2 matrix only)
    int m0_; int m1_; int m2_;          // modes
};

__global__ __launch_bounds__(256, 2) void gemm_mma3(
    const __half* __restrict__ Ah, const __half* __restrict__ WhBase,
    const __half* __restrict__ WlBase, GemmOut P)
{
    extern __shared__ __half gsm[];
    const uint32_t gb = smem_u32(gsm);
    const int tid  = threadIdx.x;
    const int lane = tid & 31;
    const int warp = tid >> 5;
    const int wm = warp >> 1, wn = warp & 1;
    const int mat = blockIdx.x >> 3;
    const int n0 = (blockIdx.x & 7) * 128;
    const int m0 = blockIdx.y * 128;

    const __half* Bh = WhBase + (size_t)mat * (1024*1024);
    const __half* Bl = WlBase + (size_t)mat * (1024*1024);
    const float* bias = (mat == 0) ? P.b0 : (mat == 1) ? P.b1 : P.b2;
    float* C          = (mat == 0) ? P.C0 : (mat == 1) ? P.C1 : P.C2;
    const int mode    = (mat == 0) ? P.m0_ : (mat == 1) ? P.m1_ : P.m2_;

    auto fill = [&](int s, int kt) {
        const uint32_t sbase = gb + (uint32_t)s * GSTAGE * 2;
#pragma unroll
        for (int e = 0; e < 2; e++) {               // A hi: 512 16B-chunks
            int cid = tid + e * 256;
            int r = cid >> 2, qq = cid & 3;
            const __half* src = Ah + (size_t)(m0 + r) * 1024 + kt + qq * 8;
            CP_ASYNC16(sbase + (uint32_t)(r * GSTR + qq * 8) * 2, src);
        }
#pragma unroll
        for (int e = 0; e < 4; e++) {               // B hi/lo: 1024 chunks
            int cid = tid + e * 256;
            int a = cid >> 9, r = (cid >> 2) & 127, qq = cid & 3;
            const __half* src = (a ? Bl : Bh) + (size_t)(n0 + r) * 1024 + kt + qq * 8;
            CP_ASYNC16(sbase + (uint32_t)((1 + a) * GARR + r * GSTR + qq * 8) * 2, src);
        }
    };

    float acc[2][8][4];
#pragma unroll
    for (int i = 0; i < 2; i++)
#pragma unroll
        for (int j = 0; j < 8; j++)
#pragma unroll
            for (int c = 0; c < 4; c++) acc[i][j][c] = 0.f;

    fill(0, 0);  CP_COMMIT();
    fill(1, 32); CP_COMMIT();

    // B x4 lane offset: bit3 -> k-half, bit4 -> n sub-block
    const int bln = ((lane >> 4) & 1) * 8 + (lane & 7);
    const int blk = ((lane >> 3) & 1) * 8;

    for (int c = 0; c < 32; c++) {
        const int s = c % 3;
        CP_WAIT(1);
        __syncthreads();

        const uint32_t ah_b = gb + (uint32_t)s * GSTAGE * 2;
        const uint32_t bh_b = ah_b + (uint32_t)GARR * 2;
        const uint32_t bl_b = ah_b + (uint32_t)(2 * GARR) * 2;

#pragma unroll
        for (int ks = 0; ks < 2; ks++) {
            uint32_t afh[2][4];
#pragma unroll
            for (int mt = 0; mt < 2; mt++) {
                uint32_t off = (uint32_t)((wm*32 + mt*16 + (lane & 15)) * GSTR
                                          + ks*16 + (lane >> 4) * 8) * 2;
                ldsm_x4(afh[mt], ah_b + off);
            }
#pragma unroll
            for (int tp = 0; tp < 4; tp++) {        // n-tile pairs
                uint32_t off = (uint32_t)((wn*64 + tp*16 + bln) * GSTR
                                          + ks*16 + blk) * 2;
                uint32_t b4h[4], b4l[4];
                ldsm_x4(b4h, bh_b + off);
                ldsm_x4(b4l, bl_b + off);
#pragma unroll
                for (int mt = 0; mt < 2; mt++) {
                    mma16816(acc[mt][2*tp],   afh[mt][0], afh[mt][1], afh[mt][2], afh[mt][3], b4h[0], b4h[1]);
                    mma16816(acc[mt][2*tp],   afh[mt][0], afh[mt][1], afh[mt][2], afh[mt][3], b4l[0], b4l[1]);
                    mma16816(acc[mt][2*tp+1], afh[mt][0], afh[mt][1], afh[mt][2], afh[mt][3], b4h[2], b4h[3]);
                    mma16816(acc[mt][2*tp+1], afh[mt][0], afh[mt][1], afh[mt][2], afh[mt][3], b4l[2], b4l[3]);
                }
            }
        }
        if (c + 2 < 32) fill((c + 2) % 3, (c + 2) * 32);
        CP_COMMIT();
    }

    // epilogue
#pragma unroll
    for (int mt = 0; mt < 2; mt++) {
        int r_lo = m0 + wm*32 + mt*16 + (lane >> 2);
        int r_hi = r_lo + 8;
#pragma unroll
        for (int nt = 0; nt < 8; nt++) {
            int col = n0 + wn*64 + nt*8 + (lane & 3) * 2;
            float bx = bias[col], by = bias[col + 1];
            float2 lo = make_float2(acc[mt][nt][0] + bx, acc[mt][nt][1] + by);
            float2 hi = make_float2(acc[mt][nt][2] + bx, acc[mt][nt][3] + by);
            if (mode == 0) {
                *(float2*)&C[(size_t)r_lo * 1024 + col] = lo;
                *(float2*)&C[(size_t)r_hi * 1024 + col] = hi;
            } else {
                int h = col >> 6, d = col & 63;
                int b_lo = r_lo >> 11, l_lo = r_lo & 2047;
                int b_hi = r_hi >> 11, l_hi = r_hi & 2047;
                size_t i_lo = (size_t)((b_lo*N_HEADS + h)*SEQ_L + l_lo)*HEAD_DIM + d;
                size_t i_hi = (size_t)((b_hi*N_HEADS + h)*SEQ_L + l_hi)*HEAD_DIM + d;
                *(float2*)&C[i_lo] = lo;
                *(float2*)&C[i_hi] = hi;
                if (mode == 2) {
                    __half h0,h1,l0,l1;
                    hsplit(lo.x, h0, l0); hsplit(lo.y, h1, l1);
                    *(__half2*)&P.Ch[i_lo] = __halves2half2(h0, h1);
                    *(__half2*)&P.Cl[i_lo] = __halves2half2(l0, l1);
                    hsplit(hi.x, h0, l0); hsplit(hi.y, h1, l1);
                    *(__half2*)&P.Ch[i_hi] = __halves2half2(h0, h1);
                    *(__half2*)&P.Cl[i_hi] = __halves2half2(l0, l1);
                }
            }
        }
    }
}

// ===========================================================================
// RoPE: q fp32 -> qh fp16; k fp32 -> k fp32 (output) + kh/kl halves
// ===========================================================================
__global__ __launch_bounds__(256) void rope_kernel(
    const float* __restrict__ q, float* __restrict__ k,
    __half* __restrict__ qh,
    __half* __restrict__ kh, __half* __restrict__ kl,
    const int* __restrict__ dt)
{
    int idx = blockIdx.x * blockDim.x + threadIdx.x;
    int i  = idx & 31;
    int l  = (idx >> 5) & (SEQ_L-1);
    int bh = idx >> 16;
    float t = (float)dt[l >> 7];
    float ang = t * __expf(-(float)i * (11.512925464970229f / 32.0f));
    float s, c;
    __sincosf(ang, &s, &c);
    size_t base = (size_t)(bh*SEQ_L + l)*HEAD_DIM + i;

    float q0 = q[base], q1 = q[base+32];
    qh[base]    = __float2half_rn(q0*c - q1*s);
    qh[base+32] = __float2half_rn(q1*c + q0*s);

    float k0 = k[base], k1 = k[base+32];
    float kr0 = k0*c - k1*s, kr1 = k1*c + k0*s;
    k[base] = kr0; k[base+32] = kr1;
    __half hh, hl;
    hsplit(kr0, hh, hl); kh[base]    = hh; kl[base]    = hl;
    hsplit(kr1, hh, hl); kh[base+32] = hh; kl[base+32] = hl;
}

// ===========================================================================
// Flash attention fp16x2: S = Qh*(Kh+Kl), PV = P*(Vh+Vl).
// M=128 q-rows, 8 warps, Tk=64, 2-stage cp.async KV, 2 CTA/SM, x4 ldsm.
// ===========================================================================
#define FSTR 72
#define FQ   (128*FSTR)
#define FK   (64*FSTR)
#define FLASH_SMEM ((FQ + 8*FK)*2)    // 92160 B

__global__ __launch_bounds__(256, 2) void flash_mma(
    const __half* __restrict__ qh,
    const __half* __restrict__ kh, const __half* __restrict__ kl,
    const __half* __restrict__ vh, const __half* __restrict__ vl,
    __half* __restrict__ oh)
{
    extern __shared__ __half fsm[];
    const uint32_t fb = smem_u32(fsm);
    const int tid  = threadIdx.x;
    const int lane = tid & 31;
    const int warp = tid >> 5;
    const int b = blockIdx.z, h = blockIdx.y;
    const int qbase = blockIdx.x * 128;
    const size_t bh_off = (size_t)(b*N_HEADS + h)*KV_STRIDE;

    const __half* kv_src[4] = { kh + bh_off, kl + bh_off, vh + bh_off, vl + bh_off };

#pragma unroll
    for (int e = 0; e < 4; e++) {
        int cid = tid + e * 256;
        int r = cid >> 3, qq = cid & 7;
        const __half* src = qh + bh_off + (size_t)(qbase + r) * 64 + qq * 8;
        CP_ASYNC16(fb + (uint32_t)(r*FSTR + qq*8) * 2, src);
    }
    CP_COMMIT();

    auto fillKV = [&](int s, int kt) {
#pragma unroll
        for (int e = 0; e < 8; e++) {
            int cid = tid + e * 256;
            int a = cid >> 9, r = (cid >> 3) & 63, qq = cid & 7;
            const __half* src = kv_src[a] + (size_t)(kt + r) * 64 + qq * 8;
            CP_ASYNC16(fb + (uint32_t)(FQ + (s*4 + a)*FK + r*FSTR + qq*8) * 2, src);
        }
    };
    fillKV(0, 0);  CP_COMMIT();
    fillKV(1, 64); CP_COMMIT();

    CP_WAIT(2);
    __syncthreads();

    uint32_t qfh[4][4];
#pragma unroll
    for (int s = 0; s < 4; s++) {
        uint32_t off = (uint32_t)((warp*16 + (lane & 15)) * FSTR
                                  + s*16 + (lane >> 4) * 8) * 2;
        ldsm_x4(qfh[s], fb + off);
    }

    float oacc[8][4];
#pragma unroll
    for (int n = 0; n < 8; n++)
#pragma unroll
        for (int c = 0; c < 4; c++) oacc[n][c] = 0.f;
    float m_lo = -1e30f, m_hi = -1e30f;
    float l_lo = 0.f, l_hi = 0.f;
    const float scale = 0.125f;

    // x4 lane offsets
    const int bln = ((lane >> 4) & 1) * 8 + (lane & 7);   // K: n sub-block + row
    const int blk = ((lane >> 3) & 1) * 8;                // K: k-half
    const int vrow = ((lane >> 3) & 1) * 8 + (lane & 7);  // V: k row within 16
    const int vcol = ((lane >> 4) & 1);                   // V: n sub-block

    for (int c = 0; c < 32; c++) {
        const int s = c & 1;
        if (c < 31) { CP_WAIT(1); } else { CP_WAIT(0); }
        __syncthreads();

        const uint32_t kh_b = fb + (uint32_t)(FQ + (s*4 + 0)*FK) * 2;
        const uint32_t kl_b = fb + (uint32_t)(FQ + (s*4 + 1)*FK) * 2;
        const uint32_t vh_b = fb + (uint32_t)(FQ + (s*4 + 2)*FK) * 2;
        const uint32_t vl_b = fb + (uint32_t)(FQ + (s*4 + 3)*FK) * 2;

        // S = Qh * (Kh + Kl), j-tile pairs via x4
        float sacc[8][4];
#pragma unroll
        for (int j = 0; j < 8; j++)
#pragma unroll
            for (int cc = 0; cc < 4; cc++) sacc[j][cc] = 0.f;
#pragma unroll
        for (int jp = 0; jp < 4; jp++) {
#pragma unroll
            for (int ks = 0; ks < 4; ks++) {
                uint32_t off = (uint32_t)((jp*16 + bln) * FSTR + ks*16 + blk) * 2;
                uint32_t k4h[4], k4l[4];
                ldsm_x4(k4h, kh_b + off);
                ldsm_x4(k4l, kl_b + off);
                mma16816(sacc[2*jp],   qfh[ks][0], qfh[ks][1], qfh[ks][2], qfh[ks][3], k4h[0], k4h[1]);
                mma16816(sacc[2*jp],   qfh[ks][0], qfh[ks][1], qfh[ks][2], qfh[ks][3], k4l[0], k4l[1]);
                mma16816(sacc[2*jp+1], qfh[ks][0], qfh[ks][1], qfh[ks][2], qfh[ks][3], k4h[2], k4h[3]);
                mma16816(sacc[2*jp+1], qfh[ks][0], qfh[ks][1], qfh[ks][2], qfh[ks][3], k4l[2], k4l[3]);
            }
        }

        // online softmax
        float mx0 = -1e30f, mx1 = -1e30f;
#pragma unroll
        for (int j = 0; j < 8; j++) {
            mx0 = fmaxf(mx0, fmaxf(sacc[j][0], sacc[j][1]));
            mx1 = fmaxf(mx1, fmaxf(sacc[j][2], sacc[j][3]));
        }
        mx0 = fmaxf(mx0, __shfl_xor_sync(0xffffffffu, mx0, 1));
        mx0 = fmaxf(mx0, __shfl_xor_sync(0xffffffffu, mx0, 2));
        mx1 = fmaxf(mx1, __shfl_xor_sync(0xffffffffu, mx1, 1));
        mx1 = fmaxf(mx1, __shfl_xor_sync(0xffffffffu, mx1, 2));
        float mn0 = fmaxf(m_lo, mx0 * scale);
        float mn1 = fmaxf(m_hi, mx1 * scale);
        float al0 = __expf(m_lo - mn0);
        float al1 = __expf(m_hi - mn1);
        m_lo = mn0; m_hi = mn1;
        float sum0 = 0.f, sum1 = 0.f;
#pragma unroll
        for (int j = 0; j < 8; j++) {
            sacc[j][0] = __expf(sacc[j][0] * scale - mn0);
            sacc[j][1] = __expf(sacc[j][1] * scale - mn0);
            sacc[j][2] = __expf(sacc[j][2] * scale - mn1);
            sacc[j][3] = __expf(sacc[j][3] * scale - mn1);
            sum0 += sacc[j][0] + sacc[j][1];
            sum1 += sacc[j][2] + sacc[j][3];
        }
        sum0 += __shfl_xor_sync(0xffffffffu, sum0, 1);
        sum0 += __shfl_xor_sync(0xffffffffu, sum0, 2);
        sum1 += __shfl_xor_sync(0xffffffffu, sum1, 1);
        sum1 += __shfl_xor_sync(0xffffffffu, sum1, 2);
        l_lo = l_lo * al0 + sum0;
        l_hi = l_hi * al1 + sum1;
#pragma unroll
        for (int n = 0; n < 8; n++) {
            oacc[n][0] *= al0; oacc[n][1] *= al0;
            oacc[n][2] *= al1; oacc[n][3] *= al1;
        }

        // PV: P (fp16) x (Vh + Vl), n-pairs via x4 trans
#pragma unroll
        for (int t = 0; t < 4; t++) {
            uint32_t a0 = pack_h2(sacc[2*t][0],   sacc[2*t][1]);
            uint32_t a1 = pack_h2(sacc[2*t][2],   sacc[2*t][3]);
            uint32_t a2 = pack_h2(sacc[2*t+1][0], sacc[2*t+1][1]);
            uint32_t a3 = pack_h2(sacc[2*t+1][2], sacc[2*t+1][3]);
#pragma unroll
            for (int u = 0; u < 4; u++) {
                uint32_t off = (uint32_t)((t*16 + vrow) * FSTR + (u*2 + vcol)*8) * 2;
                uint32_t v4[4];
                ldsm_x4t(v4, vh_b + off);
                mma16816(oacc[2*u],   a0, a1, a2, a3, v4[0], v4[1]);
                mma16816(oacc[2*u+1], a0, a1, a2, a3, v4[2], v4[3]);
                ldsm_x4t(v4, vl_b + off);
                mma16816(oacc[2*u],   a0, a1, a2, a3, v4[0], v4[1]);
                mma16816(oacc[2*u+1], a0, a1, a2, a3, v4[2], v4[3]);
            }
        }

        __syncthreads();
        if (c + 2 < 32) { fillKV(s, (c + 2) * 64); CP_COMMIT(); }
    }

    // normalize + write fp16 (flat (b, l, h*64+d))
    float inv0 = 1.0f / l_lo;
    float inv1 = 1.0f / l_hi;
    int r_lo = qbase + warp*16 + (lane >> 2);
    int r_hi = r_lo + 8;
#pragma unroll
    for (int n = 0; n < 8; n++) {
        int col = h*HEAD_DIM + n*8 + (lane & 3)*2;
        size_t i_lo = (size_t)(b*SEQ_L + r_lo)*D_MODEL + col;
        size_t i_hi = (size_t)(b*SEQ_L + r_hi)*D_MODEL + col;
        *(__half2*)&oh[i_lo] = __floats2half2_rn(oacc[n][0]*inv0, oacc[n][1]*inv0);
        *(__half2*)&oh[i_hi] = __floats2half2_rn(oacc[n][2]*inv1, oacc[n][3]*inv1);
    }
}

// ---------------------------------------------------------------------------
extern "C" void kernel_launch(void* const* d_in, const int* in_sizes, int n_in,
                              void* d_out, int out_size)
{
    const float* x  = (const float*)d_in[0];
    const int*   dt = (const int*)  d_in[1];
    const float* Wq = (const float*)d_in[2];
    const float* bq = (const float*)d_in[3];
    const float* Wk = (const float*)d_in[4];
    const float* bk = (const float*)d_in[5];
    const float* Wv = (const float*)d_in[6];
    const float* bv = (const float*)d_in[7];
    const float* Wo = (const float*)d_in[8];
    const float* bo = (const float*)d_in[9];

    float* outp  = (float*)d_out;
    float* k_out = outp  + NELEM;
    float* v_out = k_out + NELEM;

    float *qbuf;
    __half *xh,*wh,*wl,*qh,*kh,*kl,*vh,*vl,*ah;
    cudaGetSymbolAddress((void**)&qbuf, g_q);
    cudaGetSymbolAddress((void**)&xh, g_xh);
    cudaGetSymbolAddress((void**)&wh, g_wh); cudaGetSymbolAddress((void**)&wl, g_wl);
    cudaGetSymbolAddress((void**)&qh, g_qh);
    cudaGetSymbolAddress((void**)&kh, g_kh); cudaGetSymbolAddress((void**)&kl, g_kl);
    cudaGetSymbolAddress((void**)&vh, g_vh); cudaGetSymbolAddress((void**)&vl, g_vl);
    cudaGetSymbolAddress((void**)&ah, g_ah);

    cudaFuncSetAttribute(gemm_mma3, cudaFuncAttributeMaxDynamicSharedMemorySize, GEMM_SMEM);
    cudaFuncSetAttribute(flash_mma, cudaFuncAttributeMaxDynamicSharedMemorySize, FLASH_SMEM);

    const size_t WSZ = 1024*1024;
    split_hi_kernel<<<4096, 256>>>(x, xh, (int)(NELEM/4));
    split4_kernel<<<4096, 256>>>(Wq, Wk, Wv, Wo, wh, wl);

    // fused QKV projections: one launch, mats 0..2
    GemmOut Pqkv;
    Pqkv.b0 = bq; Pqkv.b1 = bk; Pqkv.b2 = bv;
    Pqkv.C0 = qbuf; Pqkv.C1 = k_out; Pqkv.C2 = v_out;
    Pqkv.Ch = vh; Pqkv.Cl = vl;
    Pqkv.m0_ = 1; Pqkv.m1_ = 1; Pqkv.m2_ = 2;
    gemm_mma3<<<dim3(24, 32), 256, GEMM_SMEM>>>(xh, wh, wl, Pqkv);

    rope_kernel<<<8192, 256>>>(qbuf, k_out, qh, kh, kl, dt);

    flash_mma<<<dim3(SEQ_L/128, N_HEADS, BATCH), 256, FLASH_SMEM>>>(
        qh, kh, kl, vh, vl, ah);

    // output projection (mat 0 of Wo slice)
    GemmOut Po;
    Po.b0 = bo; Po.b1 = nullptr; Po.b2 = nullptr;
    Po.C0 = outp; Po.C1 = nullptr; Po.C2 = nullptr;
    Po.Ch = nullptr; Po.Cl = nullptr;
    Po.m0_ = 0; Po.m1_ = 0; Po.m2_ = 0;
    gemm_mma3<<<dim3(8, 32), 256, GEMM_SMEM>>>(ah, wh + 3*WSZ, wl + 3*WSZ, Po);
}

// round 7
// speedup vs baseline: 5.4854x; 1.2530x over previous
#include <cuda_runtime.h>
#include <cuda_fp16.h>
#include <cstdint>

#define D_MODEL   1024
#define N_HEADS   16
#define HEAD_DIM  64
#define SEQ_L     2048
#define BATCH     2
#define BL        (BATCH*SEQ_L)
#define KV_STRIDE (SEQ_L*HEAD_DIM)
#define NELEM     ((size_t)BL*D_MODEL)   // 4M

// static scratch (allocation-free)
__device__ float  g_q [BATCH*N_HEADS*SEQ_L*HEAD_DIM];        // q fp32 (pre-rope)
__device__ __half g_xh[NELEM];                               // x rounded to fp16
__device__ __half g_wh[4][1024*1024], g_wl[4][1024*1024];    // W hi/lo (contiguous)
__device__ __half g_qh[NELEM];                               // q fp16 (post-rope)
__device__ __half g_kh[NELEM];                               // k fp16 (post-rope)
__device__ __half g_vh[NELEM];                               // v fp16
__device__ __half g_ah[NELEM];                               // attn out fp16

// ===========================================================================
// helpers
// ===========================================================================
__device__ __forceinline__ uint32_t smem_u32(const void* p) {
    uint32_t a;
    asm("{ .reg .u64 t; cvta.to.shared.u64 t, %1; cvt.u32.u64 %0, t; }"
        : "=r"(a) : "l"(p));
    return a;
}
__device__ __forceinline__ void ldsm_x4(uint32_t* r, uint32_t addr) {
    asm volatile("ldmatrix.sync.aligned.m8n8.x4.shared.b16 {%0,%1,%2,%3}, [%4];"
                 : "=r"(r[0]), "=r"(r[1]), "=r"(r[2]), "=r"(r[3]) : "r"(addr));
}
__device__ __forceinline__ void ldsm_x4t(uint32_t* r, uint32_t addr) {
    asm volatile("ldmatrix.sync.aligned.m8n8.x4.trans.shared.b16 {%0,%1,%2,%3}, [%4];"
                 : "=r"(r[0]), "=r"(r[1]), "=r"(r[2]), "=r"(r[3]) : "r"(addr));
}
__device__ __forceinline__ void mma16816(float* c,
    uint32_t a0, uint32_t a1, uint32_t a2, uint32_t a3, uint32_t b0, uint32_t b1) {
    asm volatile(
        "mma.sync.aligned.m16n8k16.row.col.f32.f16.f16.f32 "
        "{%0,%1,%2,%3}, {%4,%5,%6,%7}, {%8,%9}, {%0,%1,%2,%3};"
        : "+f"(c[0]), "+f"(c[1]), "+f"(c[2]), "+f"(c[3])
        : "r"(a0), "r"(a1), "r"(a2), "r"(a3), "r"(b0), "r"(b1));
}
__device__ __forceinline__ uint32_t pack_h2(float a, float b) {
    __half2 h = __floats2half2_rn(a, b);
    return *(uint32_t*)&h;
}
__device__ __forceinline__ void hsplit(float x, __half& h, __half& l) {
    h = __float2half_rn(x);
    l = __float2half_rn(x - __half2float(h));
}
#define CP_ASYNC16(dst, src) \
    asm volatile("cp.async.cg.shared.global [%0], [%1], 16;" :: "r"(dst), "l"(src))
#define CP_COMMIT() asm volatile("cp.async.commit_group;" ::: "memory")
#define CP_WAIT(n)  asm volatile("cp.async.wait_group %0;" :: "n"(n) : "memory")

// ===========================================================================
// splits
// ===========================================================================
__global__ __launch_bounds__(256) void split_hi_kernel(
    const float* __restrict__ src, __half* __restrict__ hi, int n4)
{
    int i = blockIdx.x * blockDim.x + threadIdx.x;
    if (i >= n4) return;
    float4 v = ((const float4*)src)[i];
    ((__half2*)hi)[2*i]   = __floats2half2_rn(v.x, v.y);
    ((__half2*)hi)[2*i+1] = __floats2half2_rn(v.z, v.w);
}

__global__ __launch_bounds__(256) void split4_kernel(
    const float* __restrict__ w0, const float* __restrict__ w1,
    const float* __restrict__ w2, const float* __restrict__ w3,
    __half* __restrict__ hi, __half* __restrict__ lo)
{
    int i = blockIdx.x * blockDim.x + threadIdx.x;   // 0 .. 4*262144-1
    int m = i >> 18;
    int j = i & 262143;
    const float* src = (m == 0) ? w0 : (m == 1) ? w1 : (m == 2) ? w2 : w3;
    float4 v = ((const float4*)src)[j];
    __half h0,h1,h2,h3,l0,l1,l2,l3;
    hsplit(v.x,h0,l0); hsplit(v.y,h1,l1); hsplit(v.z,h2,l2); hsplit(v.w,h3,l3);
    size_t o = (size_t)m * 262144 + j;
    ((__half2*)hi)[2*o]   = __halves2half2(h0,h1);
    ((__half2*)hi)[2*o+1] = __halves2half2(h2,h3);
    ((__half2*)lo)[2*o]   = __halves2half2(l0,l1);
    ((__half2*)lo)[2*o+1] = __halves2half2(l2,l3);
}

// ===========================================================================
// GEMM fp16x2, fused multi-matrix: C_mat = A @ W_mat^T + bias_mat
// CTA 128x128, 8 warps (4Mx2N), k-chunk 32, 3-buffer cp.async (distance 2),
// one barrier per chunk, ldsm x4. 2 CTA/SM.
// per-matrix mode: 0 flat fp32, 1 head-major fp32, 2 head-major fp32 + fp16
// ===========================================================================
#define GSTR 40
#define GARR (128*GSTR)                 // halves per array (5120)
#define GSTAGE (3*GARR)                 // halves per stage
#define GEMM_SMEM (3*GSTAGE*2)          // 92160 B

struct GemmOut {
    const float* b0; const float* b1; const float* b2;
    float* C0; float* C1; float* C2;
    __half* Ch;                          // fp16 output (mode 2 matrix only)
    int m0_; int m1_; int m2_;           // modes
};

__global__ __launch_bounds__(256, 2) void gemm_mma3(
    const __half* __restrict__ Ah, const __half* __restrict__ WhBase,
    const __half* __restrict__ WlBase, GemmOut P)
{
    extern __shared__ __half gsm[];
    const uint32_t gb = smem_u32(gsm);
    const int tid  = threadIdx.x;
    const int lane = tid & 31;
    const int warp = tid >> 5;
    const int wm = warp >> 1, wn = warp & 1;
    const int mat = blockIdx.x >> 3;
    const int n0 = (blockIdx.x & 7) * 128;
    const int m0 = blockIdx.y * 128;

    const __half* Bh = WhBase + (size_t)mat * (1024*1024);
    const __half* Bl = WlBase + (size_t)mat * (1024*1024);
    const float* bias = (mat == 0) ? P.b0 : (mat == 1) ? P.b1 : P.b2;
    float* C          = (mat == 0) ? P.C0 : (mat == 1) ? P.C1 : P.C2;
    const int mode    = (mat == 0) ? P.m0_ : (mat == 1) ? P.m1_ : P.m2_;

    auto fill = [&](int s, int kt) {
        const uint32_t sbase = gb + (uint32_t)s * GSTAGE * 2;
#pragma unroll
        for (int e = 0; e < 2; e++) {               // A hi: 512 16B-chunks
            int cid = tid + e * 256;
            int r = cid >> 2, qq = cid & 3;
            const __half* src = Ah + (size_t)(m0 + r) * 1024 + kt + qq * 8;
            CP_ASYNC16(sbase + (uint32_t)(r * GSTR + qq * 8) * 2, src);
        }
#pragma unroll
        for (int e = 0; e < 4; e++) {               // B hi/lo: 1024 chunks
            int cid = tid + e * 256;
            int a = cid >> 9, r = (cid >> 2) & 127, qq = cid & 3;
            const __half* src = (a ? Bl : Bh) + (size_t)(n0 + r) * 1024 + kt + qq * 8;
            CP_ASYNC16(sbase + (uint32_t)((1 + a) * GARR + r * GSTR + qq * 8) * 2, src);
        }
    };

    float acc[2][8][4];
#pragma unroll
    for (int i = 0; i < 2; i++)
#pragma unroll
        for (int j = 0; j < 8; j++)
#pragma unroll
            for (int c = 0; c < 4; c++) acc[i][j][c] = 0.f;

    fill(0, 0);  CP_COMMIT();
    fill(1, 32); CP_COMMIT();

    const int bln = ((lane >> 4) & 1) * 8 + (lane & 7);
    const int blk = ((lane >> 3) & 1) * 8;

    for (int c = 0; c < 32; c++) {
        const int s = c % 3;
        CP_WAIT(1);
        __syncthreads();

        const uint32_t ah_b = gb + (uint32_t)s * GSTAGE * 2;
        const uint32_t bh_b = ah_b + (uint32_t)GARR * 2;
        const uint32_t bl_b = ah_b + (uint32_t)(2 * GARR) * 2;

#pragma unroll
        for (int ks = 0; ks < 2; ks++) {
            uint32_t afh[2][4];
#pragma unroll
            for (int mt = 0; mt < 2; mt++) {
                uint32_t off = (uint32_t)((wm*32 + mt*16 + (lane & 15)) * GSTR
                                          + ks*16 + (lane >> 4) * 8) * 2;
                ldsm_x4(afh[mt], ah_b + off);
            }
#pragma unroll
            for (int tp = 0; tp < 4; tp++) {
                uint32_t off = (uint32_t)((wn*64 + tp*16 + bln) * GSTR
                                          + ks*16 + blk) * 2;
                uint32_t b4h[4], b4l[4];
                ldsm_x4(b4h, bh_b + off);
                ldsm_x4(b4l, bl_b + off);
#pragma unroll
                for (int mt = 0; mt < 2; mt++) {
                    mma16816(acc[mt][2*tp],   afh[mt][0], afh[mt][1], afh[mt][2], afh[mt][3], b4h[0], b4h[1]);
                    mma16816(acc[mt][2*tp],   afh[mt][0], afh[mt][1], afh[mt][2], afh[mt][3], b4l[0], b4l[1]);
                    mma16816(acc[mt][2*tp+1], afh[mt][0], afh[mt][1], afh[mt][2], afh[mt][3], b4h[2], b4h[3]);
                    mma16816(acc[mt][2*tp+1], afh[mt][0], afh[mt][1], afh[mt][2], afh[mt][3], b4l[2], b4l[3]);
                }
            }
        }
        if (c + 2 < 32) fill((c + 2) % 3, (c + 2) * 32);
        CP_COMMIT();
    }

    // epilogue
#pragma unroll
    for (int mt = 0; mt < 2; mt++) {
        int r_lo = m0 + wm*32 + mt*16 + (lane >> 2);
        int r_hi = r_lo + 8;
#pragma unroll
        for (int nt = 0; nt < 8; nt++) {
            int col = n0 + wn*64 + nt*8 + (lane & 3) * 2;
            float bx = bias[col], by = bias[col + 1];
            float2 lo = make_float2(acc[mt][nt][0] + bx, acc[mt][nt][1] + by);
            float2 hi = make_float2(acc[mt][nt][2] + bx, acc[mt][nt][3] + by);
            if (mode == 0) {
                *(float2*)&C[(size_t)r_lo * 1024 + col] = lo;
                *(float2*)&C[(size_t)r_hi * 1024 + col] = hi;
            } else {
                int h = col >> 6, d = col & 63;
                int b_lo = r_lo >> 11, l_lo = r_lo & 2047;
                int b_hi = r_hi >> 11, l_hi = r_hi & 2047;
                size_t i_lo = (size_t)((b_lo*N_HEADS + h)*SEQ_L + l_lo)*HEAD_DIM + d;
                size_t i_hi = (size_t)((b_hi*N_HEADS + h)*SEQ_L + l_hi)*HEAD_DIM + d;
                *(float2*)&C[i_lo] = lo;
                *(float2*)&C[i_hi] = hi;
                if (mode == 2) {
                    *(__half2*)&P.Ch[i_lo] = __floats2half2_rn(lo.x, lo.y);
                    *(__half2*)&P.Ch[i_hi] = __floats2half2_rn(hi.x, hi.y);
                }
            }
        }
    }
}

// ===========================================================================
// RoPE: q fp32 -> qh fp16; k fp32 -> k fp32 (output) + kh fp16
// ===========================================================================
__global__ __launch_bounds__(256) void rope_kernel(
    const float* __restrict__ q, float* __restrict__ k,
    __half* __restrict__ qh, __half* __restrict__ kh,
    const int* __restrict__ dt)
{
    int idx = blockIdx.x * blockDim.x + threadIdx.x;
    int i  = idx & 31;
    int l  = (idx >> 5) & (SEQ_L-1);
    int bh = idx >> 16;
    float t = (float)dt[l >> 7];
    float ang = t * __expf(-(float)i * (11.512925464970229f / 32.0f));
    float s, c;
    __sincosf(ang, &s, &c);
    size_t base = (size_t)(bh*SEQ_L + l)*HEAD_DIM + i;

    float q0 = q[base], q1 = q[base+32];
    qh[base]    = __float2half_rn(q0*c - q1*s);
    qh[base+32] = __float2half_rn(q1*c + q0*s);

    float k0 = k[base], k1 = k[base+32];
    float kr0 = k0*c - k1*s, kr1 = k1*c + k0*s;
    k[base] = kr0; k[base+32] = kr1;
    kh[base]    = __float2half_rn(kr0);
    kh[base+32] = __float2half_rn(kr1);
}

// ===========================================================================
// Flash attention, pure fp16 Q/K/V. M=128 q-rows, 8 warps, Tk=64,
// 3-stage cp.async KV (distance 2, one barrier/iter), 2 CTA/SM, x4 ldsm.
// ===========================================================================
#define FSTR 72
#define FQ   (128*FSTR)
#define FK   (64*FSTR)
#define FLASH_SMEM ((FQ + 6*FK)*2)    // 73728 B

__global__ __launch_bounds__(256, 2) void flash_mma(
    const __half* __restrict__ qh, const __half* __restrict__ kh,
    const __half* __restrict__ vh, __half* __restrict__ oh)
{
    extern __shared__ __half fsm[];
    const uint32_t fb = smem_u32(fsm);
    const int tid  = threadIdx.x;
    const int lane = tid & 31;
    const int warp = tid >> 5;
    const int b = blockIdx.z, h = blockIdx.y;
    const int qbase = blockIdx.x * 128;
    const size_t bh_off = (size_t)(b*N_HEADS + h)*KV_STRIDE;

    const __half* kv_src[2] = { kh + bh_off, vh + bh_off };

#pragma unroll
    for (int e = 0; e < 4; e++) {
        int cid = tid + e * 256;
        int r = cid >> 3, qq = cid & 7;
        const __half* src = qh + bh_off + (size_t)(qbase + r) * 64 + qq * 8;
        CP_ASYNC16(fb + (uint32_t)(r*FSTR + qq*8) * 2, src);
    }
    CP_COMMIT();

    auto fillKV = [&](int s, int kt) {
#pragma unroll
        for (int e = 0; e < 4; e++) {
            int cid = tid + e * 256;                 // 0..1023
            int a = cid >> 9, r = (cid >> 3) & 63, qq = cid & 7;
            const __half* src = kv_src[a] + (size_t)(kt + r) * 64 + qq * 8;
            CP_ASYNC16(fb + (uint32_t)(FQ + (s*2 + a)*FK + r*FSTR + qq*8) * 2, src);
        }
    };
    fillKV(0, 0);  CP_COMMIT();
    fillKV(1, 64); CP_COMMIT();

    CP_WAIT(2);          // Q ready
    __syncthreads();

    uint32_t qfh[4][4];
#pragma unroll
    for (int s = 0; s < 4; s++) {
        uint32_t off = (uint32_t)((warp*16 + (lane & 15)) * FSTR
                                  + s*16 + (lane >> 4) * 8) * 2;
        ldsm_x4(qfh[s], fb + off);
    }

    float oacc[8][4];
#pragma unroll
    for (int n = 0; n < 8; n++)
#pragma unroll
        for (int c = 0; c < 4; c++) oacc[n][c] = 0.f;
    float m_lo = -1e30f, m_hi = -1e30f;
    float l_lo = 0.f, l_hi = 0.f;
    const float scale = 0.125f;

    const int bln = ((lane >> 4) & 1) * 8 + (lane & 7);   // K
    const int blk = ((lane >> 3) & 1) * 8;
    const int vrow = ((lane >> 3) & 1) * 8 + (lane & 7);  // V
    const int vcol = ((lane >> 4) & 1);

    for (int c = 0; c < 32; c++) {
        const int s = c % 3;
        CP_WAIT(1);
        __syncthreads();

        const uint32_t kh_b = fb + (uint32_t)(FQ + (s*2 + 0)*FK) * 2;
        const uint32_t vh_b = fb + (uint32_t)(FQ + (s*2 + 1)*FK) * 2;

        // S = Q K^T
        float sacc[8][4];
#pragma unroll
        for (int j = 0; j < 8; j++)
#pragma unroll
            for (int cc = 0; cc < 4; cc++) sacc[j][cc] = 0.f;
#pragma unroll
        for (int jp = 0; jp < 4; jp++) {
#pragma unroll
            for (int ks = 0; ks < 4; ks++) {
                uint32_t off = (uint32_t)((jp*16 + bln) * FSTR + ks*16 + blk) * 2;
                uint32_t k4[4];
                ldsm_x4(k4, kh_b + off);
                mma16816(sacc[2*jp],   qfh[ks][0], qfh[ks][1], qfh[ks][2], qfh[ks][3], k4[0], k4[1]);
                mma16816(sacc[2*jp+1], qfh[ks][0], qfh[ks][1], qfh[ks][2], qfh[ks][3], k4[2], k4[3]);
            }
        }

        // online softmax
        float mx0 = -1e30f, mx1 = -1e30f;
#pragma unroll
        for (int j = 0; j < 8; j++) {
            mx0 = fmaxf(mx0, fmaxf(sacc[j][0], sacc[j][1]));
            mx1 = fmaxf(mx1, fmaxf(sacc[j][2], sacc[j][3]));
        }
        mx0 = fmaxf(mx0, __shfl_xor_sync(0xffffffffu, mx0, 1));
        mx0 = fmaxf(mx0, __shfl_xor_sync(0xffffffffu, mx0, 2));
        mx1 = fmaxf(mx1, __shfl_xor_sync(0xffffffffu, mx1, 1));
        mx1 = fmaxf(mx1, __shfl_xor_sync(0xffffffffu, mx1, 2));
        float mn0 = fmaxf(m_lo, mx0 * scale);
        float mn1 = fmaxf(m_hi, mx1 * scale);
        float al0 = __expf(m_lo - mn0);
        float al1 = __expf(m_hi - mn1);
        m_lo = mn0; m_hi = mn1;
        float sum0 = 0.f, sum1 = 0.f;
#pragma unroll
        for (int j = 0; j < 8; j++) {
            sacc[j][0] = __expf(sacc[j][0] * scale - mn0);
            sacc[j][1] = __expf(sacc[j][1] * scale - mn0);
            sacc[j][2] = __expf(sacc[j][2] * scale - mn1);
            sacc[j][3] = __expf(sacc[j][3] * scale - mn1);
            sum0 += sacc[j][0] + sacc[j][1];
            sum1 += sacc[j][2] + sacc[j][3];
        }
        sum0 += __shfl_xor_sync(0xffffffffu, sum0, 1);
        sum0 += __shfl_xor_sync(0xffffffffu, sum0, 2);
        sum1 += __shfl_xor_sync(0xffffffffu, sum1, 1);
        sum1 += __shfl_xor_sync(0xffffffffu, sum1, 2);
        l_lo = l_lo * al0 + sum0;
        l_hi = l_hi * al1 + sum1;
#pragma unroll
        for (int n = 0; n < 8; n++) {
            oacc[n][0] *= al0; oacc[n][1] *= al0;
            oacc[n][2] *= al1; oacc[n][3] *= al1;
        }

        // PV
#pragma unroll
        for (int t = 0; t < 4; t++) {
            uint32_t a0 = pack_h2(sacc[2*t][0],   sacc[2*t][1]);
            uint32_t a1 = pack_h2(sacc[2*t][2],   sacc[2*t][3]);
            uint32_t a2 = pack_h2(sacc[2*t+1][0], sacc[2*t+1][1]);
            uint32_t a3 = pack_h2(sacc[2*t+1][2], sacc[2*t+1][3]);
#pragma unroll
            for (int u = 0; u < 4; u++) {
                uint32_t off = (uint32_t)((t*16 + vrow) * FSTR + (u*2 + vcol)*8) * 2;
                uint32_t v4[4];
                ldsm_x4t(v4, vh_b + off);
                mma16816(oacc[2*u],   a0, a1, a2, a3, v4[0], v4[1]);
                mma16816(oacc[2*u+1], a0, a1, a2, a3, v4[2], v4[3]);
            }
        }

        if (c + 2 < 32) fillKV((c + 2) % 3, (c + 2) * 64);
        CP_COMMIT();
    }

    // normalize + write fp16 (flat (b, l, h*64+d))
    float inv0 = 1.0f / l_lo;
    float inv1 = 1.0f / l_hi;
    int r_lo = qbase + warp*16 + (lane >> 2);
    int r_hi = r_lo + 8;
#pragma unroll
    for (int n = 0; n < 8; n++) {
        int col = h*HEAD_DIM + n*8 + (lane & 3)*2;
        size_t i_lo = (size_t)(b*SEQ_L + r_lo)*D_MODEL + col;
        size_t i_hi = (size_t)(b*SEQ_L + r_hi)*D_MODEL + col;
        *(__half2*)&oh[i_lo] = __floats2half2_rn(oacc[n][0]*inv0, oacc[n][1]*inv0);
        *(__half2*)&oh[i_hi] = __floats2half2_rn(oacc[n][2]*inv1, oacc[n][3]*inv1);
    }
}

// ---------------------------------------------------------------------------
extern "C" void kernel_launch(void* const* d_in, const int* in_sizes, int n_in,
                              void* d_out, int out_size)
{
    const float* x  = (const float*)d_in[0];
    const int*   dt = (const int*)  d_in[1];
    const float* Wq = (const float*)d_in[2];
    const float* bq = (const float*)d_in[3];
    const float* Wk = (const float*)d_in[4];
    const float* bk = (const float*)d_in[5];
    const float* Wv = (const float*)d_in[6];
    const float* bv = (const float*)d_in[7];
    const float* Wo = (const float*)d_in[8];
    const float* bo = (const float*)d_in[9];

    float* outp  = (float*)d_out;
    float* k_out = outp  + NELEM;
    float* v_out = k_out + NELEM;

    float *qbuf;
    __half *xh,*wh,*wl,*qh,*kh,*vh,*ah;
    cudaGetSymbolAddress((void**)&qbuf, g_q);
    cudaGetSymbolAddress((void**)&xh, g_xh);
    cudaGetSymbolAddress((void**)&wh, g_wh); cudaGetSymbolAddress((void**)&wl, g_wl);
    cudaGetSymbolAddress((void**)&qh, g_qh);
    cudaGetSymbolAddress((void**)&kh, g_kh);
    cudaGetSymbolAddress((void**)&vh, g_vh);
    cudaGetSymbolAddress((void**)&ah, g_ah);

    cudaFuncSetAttribute(gemm_mma3, cudaFuncAttributeMaxDynamicSharedMemorySize, GEMM_SMEM);
    cudaFuncSetAttribute(flash_mma, cudaFuncAttributeMaxDynamicSharedMemorySize, FLASH_SMEM);

    const size_t WSZ = 1024*1024;
    split_hi_kernel<<<4096, 256>>>(x, xh, (int)(NELEM/4));
    split4_kernel<<<4096, 256>>>(Wq, Wk, Wv, Wo, wh, wl);

    // fused QKV projections
    GemmOut Pqkv;
    Pqkv.b0 = bq; Pqkv.b1 = bk; Pqkv.b2 = bv;
    Pqkv.C0 = qbuf; Pqkv.C1 = k_out; Pqkv.C2 = v_out;
    Pqkv.Ch = vh;
    Pqkv.m0_ = 1; Pqkv.m1_ = 1; Pqkv.m2_ = 2;
    gemm_mma3<<<dim3(24, 32), 256, GEMM_SMEM>>>(xh, wh, wl, Pqkv);

    rope_kernel<<<8192, 256>>>(qbuf, k_out, qh, kh, dt);

    flash_mma<<<dim3(SEQ_L/128, N_HEADS, BATCH), 256, FLASH_SMEM>>>(qh, kh, vh, ah);

    // output projection
    GemmOut Po;
    Po.b0 = bo; Po.b1 = nullptr; Po.b2 = nullptr;
    Po.C0 = outp; Po.C1 = nullptr; Po.C2 = nullptr;
    Po.Ch = nullptr;
    Po.m0_ = 0; Po.m1_ = 0; Po.m2_ = 0;
    gemm_mma3<<<dim3(8, 32), 256, GEMM_SMEM>>>(ah, wh + 3*WSZ, wl + 3*WSZ, Po);
}

// round 8
// speedup vs baseline: 7.2275x; 1.3176x over previous
#include <cuda_runtime.h>
#include <cuda_fp16.h>
#include <cstdint>

#define D_MODEL   1024
#define N_HEADS   16
#define HEAD_DIM  64
#define SEQ_L     2048
#define BATCH     2
#define BL        (BATCH*SEQ_L)
#define KV_STRIDE (SEQ_L*HEAD_DIM)
#define NELEM     ((size_t)BL*D_MODEL)   // 4M

// static scratch (allocation-free)
__device__ float  g_q [BATCH*N_HEADS*SEQ_L*HEAD_DIM];        // q fp32 (pre-rope)
__device__ __half g_xh[NELEM];                               // x fp16
__device__ __half g_wh[4][1024*1024];                        // W fp16 (contiguous)
__device__ __half g_qh[NELEM];                               // q fp16 (post-rope)
__device__ __half g_kh[NELEM];                               // k fp16 (post-rope)
__device__ __half g_vh[NELEM];                               // v fp16
__device__ __half g_ah[NELEM];                               // attn out fp16

// ===========================================================================
// helpers
// ===========================================================================
__device__ __forceinline__ uint32_t smem_u32(const void* p) {
    uint32_t a;
    asm("{ .reg .u64 t; cvta.to.shared.u64 t, %1; cvt.u32.u64 %0, t; }"
        : "=r"(a) : "l"(p));
    return a;
}
__device__ __forceinline__ void ldsm_x4(uint32_t* r, uint32_t addr) {
    asm volatile("ldmatrix.sync.aligned.m8n8.x4.shared.b16 {%0,%1,%2,%3}, [%4];"
                 : "=r"(r[0]), "=r"(r[1]), "=r"(r[2]), "=r"(r[3]) : "r"(addr));
}
__device__ __forceinline__ void ldsm_x4t(uint32_t* r, uint32_t addr) {
    asm volatile("ldmatrix.sync.aligned.m8n8.x4.trans.shared.b16 {%0,%1,%2,%3}, [%4];"
                 : "=r"(r[0]), "=r"(r[1]), "=r"(r[2]), "=r"(r[3]) : "r"(addr));
}
__device__ __forceinline__ void mma16816(float* c,
    uint32_t a0, uint32_t a1, uint32_t a2, uint32_t a3, uint32_t b0, uint32_t b1) {
    asm volatile(
        "mma.sync.aligned.m16n8k16.row.col.f32.f16.f16.f32 "
        "{%0,%1,%2,%3}, {%4,%5,%6,%7}, {%8,%9}, {%0,%1,%2,%3};"
        : "+f"(c[0]), "+f"(c[1]), "+f"(c[2]), "+f"(c[3])
        : "r"(a0), "r"(a1), "r"(a2), "r"(a3), "r"(b0), "r"(b1));
}
__device__ __forceinline__ uint32_t pack_h2(float a, float b) {
    __half2 h = __floats2half2_rn(a, b);
    return *(uint32_t*)&h;
}
#define CP_ASYNC16(dst, src) \
    asm volatile("cp.async.cg.shared.global [%0], [%1], 16;" :: "r"(dst), "l"(src))
#define CP_COMMIT() asm volatile("cp.async.commit_group;" ::: "memory")
#define CP_WAIT(n)  asm volatile("cp.async.wait_group %0;" :: "n"(n) : "memory")

// ===========================================================================
// fused split: x (1M quads) + 4 W matrices (1M quads) -> fp16
// ===========================================================================
__global__ __launch_bounds__(256) void split_all_kernel(
    const float* __restrict__ x,
    const float* __restrict__ w0, const float* __restrict__ w1,
    const float* __restrict__ w2, const float* __restrict__ w3,
    __half* __restrict__ xh, __half* __restrict__ wh)
{
    int i = blockIdx.x * blockDim.x + threadIdx.x;   // 0 .. 2M-1 (quads)
    const float* src;
    __half* dst;
    size_t j;
    if (i < 1048576) {
        src = x; dst = xh; j = i;
    } else {
        int k = i - 1048576;
        int m = k >> 18;
        j = k & 262143;
        src = (m == 0) ? w0 : (m == 1) ? w1 : (m == 2) ? w2 : w3;
        dst = wh + (size_t)m * (1024*1024);
    }
    float4 v = ((const float4*)src)[j];
    ((__half2*)dst)[2*j]   = __floats2half2_rn(v.x, v.y);
    ((__half2*)dst)[2*j+1] = __floats2half2_rn(v.z, v.w);
}

// ===========================================================================
// GEMM pure fp16: C_mat = A @ W_mat^T + bias_mat (fused multi-matrix)
// CTA 128x128, 8 warps (4Mx2N), k-chunk 32, 3-buffer cp.async (distance 2),
// one barrier per chunk, ldsm x4. 2 CTA/SM.
// per-matrix mode: 0 flat fp32, 1 head-major fp32, 2 head-major fp32 + fp16
// ===========================================================================
#define GSTR 40
#define GARR (128*GSTR)                 // halves per array (5120)
#define GSTAGE (2*GARR)                 // halves per stage (A + B)
#define GEMM_SMEM (3*GSTAGE*2)          // 61440 B

struct GemmOut {
    const float* b0; const float* b1; const float* b2;
    float* C0; float* C1; float* C2;
    __half* Ch;                          // fp16 output (mode 2 matrix only)
    int m0_; int m1_; int m2_;           // modes
};

__global__ __launch_bounds__(256, 2) void gemm_mma3(
    const __half* __restrict__ Ah, const __half* __restrict__ WhBase, GemmOut P)
{
    extern __shared__ __half gsm[];
    const uint32_t gb = smem_u32(gsm);
    const int tid  = threadIdx.x;
    const int lane = tid & 31;
    const int warp = tid >> 5;
    const int wm = warp >> 1, wn = warp & 1;
    const int mat = blockIdx.x >> 3;
    const int n0 = (blockIdx.x & 7) * 128;
    const int m0 = blockIdx.y * 128;

    const __half* Bh = WhBase + (size_t)mat * (1024*1024);
    const float* bias = (mat == 0) ? P.b0 : (mat == 1) ? P.b1 : P.b2;
    float* C          = (mat == 0) ? P.C0 : (mat == 1) ? P.C1 : P.C2;
    const int mode    = (mat == 0) ? P.m0_ : (mat == 1) ? P.m1_ : P.m2_;

    auto fill = [&](int s, int kt) {
        const uint32_t sbase = gb + (uint32_t)s * GSTAGE * 2;
#pragma unroll
        for (int e = 0; e < 2; e++) {               // A: 512 16B-chunks
            int cid = tid + e * 256;
            int r = cid >> 2, qq = cid & 3;
            const __half* src = Ah + (size_t)(m0 + r) * 1024 + kt + qq * 8;
            CP_ASYNC16(sbase + (uint32_t)(r * GSTR + qq * 8) * 2, src);
        }
#pragma unroll
        for (int e = 0; e < 2; e++) {               // B: 512 chunks
            int cid = tid + e * 256;
            int r = cid >> 2, qq = cid & 3;
            const __half* src = Bh + (size_t)(n0 + r) * 1024 + kt + qq * 8;
            CP_ASYNC16(sbase + (uint32_t)(GARR + r * GSTR + qq * 8) * 2, src);
        }
    };

    float acc[2][8][4];
#pragma unroll
    for (int i = 0; i < 2; i++)
#pragma unroll
        for (int j = 0; j < 8; j++)
#pragma unroll
            for (int c = 0; c < 4; c++) acc[i][j][c] = 0.f;

    fill(0, 0);  CP_COMMIT();
    fill(1, 32); CP_COMMIT();

    const int bln = ((lane >> 4) & 1) * 8 + (lane & 7);
    const int blk = ((lane >> 3) & 1) * 8;

    for (int c = 0; c < 32; c++) {
        const int s = c % 3;
        CP_WAIT(1);
        __syncthreads();

        const uint32_t ah_b = gb + (uint32_t)s * GSTAGE * 2;
        const uint32_t bh_b = ah_b + (uint32_t)GARR * 2;

#pragma unroll
        for (int ks = 0; ks < 2; ks++) {
            uint32_t afh[2][4];
#pragma unroll
            for (int mt = 0; mt < 2; mt++) {
                uint32_t off = (uint32_t)((wm*32 + mt*16 + (lane & 15)) * GSTR
                                          + ks*16 + (lane >> 4) * 8) * 2;
                ldsm_x4(afh[mt], ah_b + off);
            }
#pragma unroll
            for (int tp = 0; tp < 4; tp++) {
                uint32_t off = (uint32_t)((wn*64 + tp*16 + bln) * GSTR
                                          + ks*16 + blk) * 2;
                uint32_t b4[4];
                ldsm_x4(b4, bh_b + off);
#pragma unroll
                for (int mt = 0; mt < 2; mt++) {
                    mma16816(acc[mt][2*tp],   afh[mt][0], afh[mt][1], afh[mt][2], afh[mt][3], b4[0], b4[1]);
                    mma16816(acc[mt][2*tp+1], afh[mt][0], afh[mt][1], afh[mt][2], afh[mt][3], b4[2], b4[3]);
                }
            }
        }
        if (c + 2 < 32) fill((c + 2) % 3, (c + 2) * 32);
        CP_COMMIT();
    }

    // epilogue
#pragma unroll
    for (int mt = 0; mt < 2; mt++) {
        int r_lo = m0 + wm*32 + mt*16 + (lane >> 2);
        int r_hi = r_lo + 8;
#pragma unroll
        for (int nt = 0; nt < 8; nt++) {
            int col = n0 + wn*64 + nt*8 + (lane & 3) * 2;
            float bx = bias[col], by = bias[col + 1];
            float2 lo = make_float2(acc[mt][nt][0] + bx, acc[mt][nt][1] + by);
            float2 hi = make_float2(acc[mt][nt][2] + bx, acc[mt][nt][3] + by);
            if (mode == 0) {
                *(float2*)&C[(size_t)r_lo * 1024 + col] = lo;
                *(float2*)&C[(size_t)r_hi * 1024 + col] = hi;
            } else {
                int h = col >> 6, d = col & 63;
                int b_lo = r_lo >> 11, l_lo = r_lo & 2047;
                int b_hi = r_hi >> 11, l_hi = r_hi & 2047;
                size_t i_lo = (size_t)((b_lo*N_HEADS + h)*SEQ_L + l_lo)*HEAD_DIM + d;
                size_t i_hi = (size_t)((b_hi*N_HEADS + h)*SEQ_L + l_hi)*HEAD_DIM + d;
                *(float2*)&C[i_lo] = lo;
                *(float2*)&C[i_hi] = hi;
                if (mode == 2) {
                    *(__half2*)&P.Ch[i_lo] = __floats2half2_rn(lo.x, lo.y);
                    *(__half2*)&P.Ch[i_hi] = __floats2half2_rn(hi.x, hi.y);
                }
            }
        }
    }
}

// ===========================================================================
// RoPE: q fp32 -> qh fp16; k fp32 -> k fp32 (output) + kh fp16
// ===========================================================================
__global__ __launch_bounds__(256) void rope_kernel(
    const float* __restrict__ q, float* __restrict__ k,
    __half* __restrict__ qh, __half* __restrict__ kh,
    const int* __restrict__ dt)
{
    int idx = blockIdx.x * blockDim.x + threadIdx.x;
    int i  = idx & 31;
    int l  = (idx >> 5) & (SEQ_L-1);
    int bh = idx >> 16;
    float t = (float)dt[l >> 7];
    float ang = t * __expf(-(float)i * (11.512925464970229f / 32.0f));
    float s, c;
    __sincosf(ang, &s, &c);
    size_t base = (size_t)(bh*SEQ_L + l)*HEAD_DIM + i;

    float q0 = q[base], q1 = q[base+32];
    qh[base]    = __float2half_rn(q0*c - q1*s);
    qh[base+32] = __float2half_rn(q1*c + q0*s);

    float k0 = k[base], k1 = k[base+32];
    float kr0 = k0*c - k1*s, kr1 = k1*c + k0*s;
    k[base] = kr0; k[base+32] = kr1;
    kh[base]    = __float2half_rn(kr0);
    kh[base+32] = __float2half_rn(kr1);
}

// ===========================================================================
// Flash attention, pure fp16 Q/K/V. M=128 q-rows, 8 warps, Tk=64,
// 3-stage cp.async KV (distance 2, one barrier/iter), 2 CTA/SM, x4 ldsm.
// ===========================================================================
#define FSTR 72
#define FQ   (128*FSTR)
#define FK   (64*FSTR)
#define FLASH_SMEM ((FQ + 6*FK)*2)    // 73728 B

__global__ __launch_bounds__(256, 2) void flash_mma(
    const __half* __restrict__ qh, const __half* __restrict__ kh,
    const __half* __restrict__ vh, __half* __restrict__ oh)
{
    extern __shared__ __half fsm[];
    const uint32_t fb = smem_u32(fsm);
    const int tid  = threadIdx.x;
    const int lane = tid & 31;
    const int warp = tid >> 5;
    const int b = blockIdx.z, h = blockIdx.y;
    const int qbase = blockIdx.x * 128;
    const size_t bh_off = (size_t)(b*N_HEADS + h)*KV_STRIDE;

    const __half* kv_src[2] = { kh + bh_off, vh + bh_off };

#pragma unroll
    for (int e = 0; e < 4; e++) {
        int cid = tid + e * 256;
        int r = cid >> 3, qq = cid & 7;
        const __half* src = qh + bh_off + (size_t)(qbase + r) * 64 + qq * 8;
        CP_ASYNC16(fb + (uint32_t)(r*FSTR + qq*8) * 2, src);
    }
    CP_COMMIT();

    auto fillKV = [&](int s, int kt) {
#pragma unroll
        for (int e = 0; e < 4; e++) {
            int cid = tid + e * 256;                 // 0..1023
            int a = cid >> 9, r = (cid >> 3) & 63, qq = cid & 7;
            const __half* src = kv_src[a] + (size_t)(kt + r) * 64 + qq * 8;
            CP_ASYNC16(fb + (uint32_t)(FQ + (s*2 + a)*FK + r*FSTR + qq*8) * 2, src);
        }
    };
    fillKV(0, 0);  CP_COMMIT();
    fillKV(1, 64); CP_COMMIT();

    CP_WAIT(2);          // Q ready
    __syncthreads();

    uint32_t qfh[4][4];
#pragma unroll
    for (int s = 0; s < 4; s++) {
        uint32_t off = (uint32_t)((warp*16 + (lane & 15)) * FSTR
                                  + s*16 + (lane >> 4) * 8) * 2;
        ldsm_x4(qfh[s], fb + off);
    }

    float oacc[8][4];
#pragma unroll
    for (int n = 0; n < 8; n++)
#pragma unroll
        for (int c = 0; c < 4; c++) oacc[n][c] = 0.f;
    float m_lo = -1e30f, m_hi = -1e30f;
    float l_lo = 0.f, l_hi = 0.f;
    const float scale = 0.125f;

    const int bln = ((lane >> 4) & 1) * 8 + (lane & 7);   // K
    const int blk = ((lane >> 3) & 1) * 8;
    const int vrow = ((lane >> 3) & 1) * 8 + (lane & 7);  // V
    const int vcol = ((lane >> 4) & 1);

    for (int c = 0; c < 32; c++) {
        const int s = c % 3;
        CP_WAIT(1);
        __syncthreads();

        const uint32_t kh_b = fb + (uint32_t)(FQ + (s*2 + 0)*FK) * 2;
        const uint32_t vh_b = fb + (uint32_t)(FQ + (s*2 + 1)*FK) * 2;

        // S = Q K^T
        float sacc[8][4];
#pragma unroll
        for (int j = 0; j < 8; j++)
#pragma unroll
            for (int cc = 0; cc < 4; cc++) sacc[j][cc] = 0.f;
#pragma unroll
        for (int jp = 0; jp < 4; jp++) {
#pragma unroll
            for (int ks = 0; ks < 4; ks++) {
                uint32_t off = (uint32_t)((jp*16 + bln) * FSTR + ks*16 + blk) * 2;
                uint32_t k4[4];
                ldsm_x4(k4, kh_b + off);
                mma16816(sacc[2*jp],   qfh[ks][0], qfh[ks][1], qfh[ks][2], qfh[ks][3], k4[0], k4[1]);
                mma16816(sacc[2*jp+1], qfh[ks][0], qfh[ks][1], qfh[ks][2], qfh[ks][3], k4[2], k4[3]);
            }
        }

        // online softmax
        float mx0 = -1e30f, mx1 = -1e30f;
#pragma unroll
        for (int j = 0; j < 8; j++) {
            mx0 = fmaxf(mx0, fmaxf(sacc[j][0], sacc[j][1]));
            mx1 = fmaxf(mx1, fmaxf(sacc[j][2], sacc[j][3]));
        }
        mx0 = fmaxf(mx0, __shfl_xor_sync(0xffffffffu, mx0, 1));
        mx0 = fmaxf(mx0, __shfl_xor_sync(0xffffffffu, mx0, 2));
        mx1 = fmaxf(mx1, __shfl_xor_sync(0xffffffffu, mx1, 1));
        mx1 = fmaxf(mx1, __shfl_xor_sync(0xffffffffu, mx1, 2));
        float mn0 = fmaxf(m_lo, mx0 * scale);
        float mn1 = fmaxf(m_hi, mx1 * scale);
        float al0 = __expf(m_lo - mn0);
        float al1 = __expf(m_hi - mn1);
        m_lo = mn0; m_hi = mn1;
        float sum0 = 0.f, sum1 = 0.f;
#pragma unroll
        for (int j = 0; j < 8; j++) {
            sacc[j][0] = __expf(sacc[j][0] * scale - mn0);
            sacc[j][1] = __expf(sacc[j][1] * scale - mn0);
            sacc[j][2] = __expf(sacc[j][2] * scale - mn1);
            sacc[j][3] = __expf(sacc[j][3] * scale - mn1);
            sum0 += sacc[j][0] + sacc[j][1];
            sum1 += sacc[j][2] + sacc[j][3];
        }
        sum0 += __shfl_xor_sync(0xffffffffu, sum0, 1);
        sum0 += __shfl_xor_sync(0xffffffffu, sum0, 2);
        sum1 += __shfl_xor_sync(0xffffffffu, sum1, 1);
        sum1 += __shfl_xor_sync(0xffffffffu, sum1, 2);
        l_lo = l_lo * al0 + sum0;
        l_hi = l_hi * al1 + sum1;
#pragma unroll
        for (int n = 0; n < 8; n++) {
            oacc[n][0] *= al0; oacc[n][1] *= al0;
            oacc[n][2] *= al1; oacc[n][3] *= al1;
        }

        // PV
#pragma unroll
        for (int t = 0; t < 4; t++) {
            uint32_t a0 = pack_h2(sacc[2*t][0],   sacc[2*t][1]);
            uint32_t a1 = pack_h2(sacc[2*t][2],   sacc[2*t][3]);
            uint32_t a2 = pack_h2(sacc[2*t+1][0], sacc[2*t+1][1]);
            uint32_t a3 = pack_h2(sacc[2*t+1][2], sacc[2*t+1][3]);
#pragma unroll
            for (int u = 0; u < 4; u++) {
                uint32_t off = (uint32_t)((t*16 + vrow) * FSTR + (u*2 + vcol)*8) * 2;
                uint32_t v4[4];
                ldsm_x4t(v4, vh_b + off);
                mma16816(oacc[2*u],   a0, a1, a2, a3, v4[0], v4[1]);
                mma16816(oacc[2*u+1], a0, a1, a2, a3, v4[2], v4[3]);
            }
        }

        if (c + 2 < 32) fillKV((c + 2) % 3, (c + 2) * 64);
        CP_COMMIT();
    }

    // normalize + write fp16 (flat (b, l, h*64+d))
    float inv0 = 1.0f / l_lo;
    float inv1 = 1.0f / l_hi;
    int r_lo = qbase + warp*16 + (lane >> 2);
    int r_hi = r_lo + 8;
#pragma unroll
    for (int n = 0; n < 8; n++) {
        int col = h*HEAD_DIM + n*8 + (lane & 3)*2;
        size_t i_lo = (size_t)(b*SEQ_L + r_lo)*D_MODEL + col;
        size_t i_hi = (size_t)(b*SEQ_L + r_hi)*D_MODEL + col;
        *(__half2*)&oh[i_lo] = __floats2half2_rn(oacc[n][0]*inv0, oacc[n][1]*inv0);
        *(__half2*)&oh[i_hi] = __floats2half2_rn(oacc[n][2]*inv1, oacc[n][3]*inv1);
    }
}

// ---------------------------------------------------------------------------
extern "C" void kernel_launch(void* const* d_in, const int* in_sizes, int n_in,
                              void* d_out, int out_size)
{
    const float* x  = (const float*)d_in[0];
    const int*   dt = (const int*)  d_in[1];
    const float* Wq = (const float*)d_in[2];
    const float* bq = (const float*)d_in[3];
    const float* Wk = (const float*)d_in[4];
    const float* bk = (const float*)d_in[5];
    const float* Wv = (const float*)d_in[6];
    const float* bv = (const float*)d_in[7];
    const float* Wo = (const float*)d_in[8];
    const float* bo = (const float*)d_in[9];

    float* outp  = (float*)d_out;
    float* k_out = outp  + NELEM;
    float* v_out = k_out + NELEM;

    float *qbuf;
    __half *xh,*wh,*qh,*kh,*vh,*ah;
    cudaGetSymbolAddress((void**)&qbuf, g_q);
    cudaGetSymbolAddress((void**)&xh, g_xh);
    cudaGetSymbolAddress((void**)&wh, g_wh);
    cudaGetSymbolAddress((void**)&qh, g_qh);
    cudaGetSymbolAddress((void**)&kh, g_kh);
    cudaGetSymbolAddress((void**)&vh, g_vh);
    cudaGetSymbolAddress((void**)&ah, g_ah);

    cudaFuncSetAttribute(gemm_mma3, cudaFuncAttributeMaxDynamicSharedMemorySize, GEMM_SMEM);
    cudaFuncSetAttribute(flash_mma, cudaFuncAttributeMaxDynamicSharedMemorySize, FLASH_SMEM);

    const size_t WSZ = 1024*1024;
    split_all_kernel<<<8192, 256>>>(x, Wq, Wk, Wv, Wo, xh, wh);

    // fused QKV projections
    GemmOut Pqkv;
    Pqkv.b0 = bq; Pqkv.b1 = bk; Pqkv.b2 = bv;
    Pqkv.C0 = qbuf; Pqkv.C1 = k_out; Pqkv.C2 = v_out;
    Pqkv.Ch = vh;
    Pqkv.m0_ = 1; Pqkv.m1_ = 1; Pqkv.m2_ = 2;
    gemm_mma3<<<dim3(24, 32), 256, GEMM_SMEM>>>(xh, wh, Pqkv);

    rope_kernel<<<8192, 256>>>(qbuf, k_out, qh, kh, dt);

    flash_mma<<<dim3(SEQ_L/128, N_HEADS, BATCH), 256, FLASH_SMEM>>>(qh, kh, vh, ah);

    // output projection
    GemmOut Po;
    Po.b0 = bo; Po.b1 = nullptr; Po.b2 = nullptr;
    Po.C0 = outp; Po.C1 = nullptr; Po.C2 = nullptr;
    Po.Ch = nullptr;
    Po.m0_ = 0; Po.m1_ = 0; Po.m2_ = 0;
    gemm_mma3<<<dim3(8, 32), 256, GEMM_SMEM>>>(ah, wh + 3*WSZ, Po);
}